// round 5
// baseline (speedup 1.0000x reference)
#include <cuda_runtime.h>
#include <cuda_bf16.h>
#include <math.h>
#include <cstdint>

// Problem constants
#define kT 4096
#define kE 1024
#define kH 16
#define kD 64

// ---------------------------------------------------------------------------
// Scratch (__device__ globals; allocation-free rule)
// ---------------------------------------------------------------------------
__device__ __nv_bfloat16 g_Xh[kT * kE];
__device__ __nv_bfloat16 g_Xl[kT * kE];
__device__ __nv_bfloat16 g_Wh[4][kE * kE];  // q,k,v,o
__device__ __nv_bfloat16 g_Wl[4][kE * kE];
__device__ __nv_bfloat16 g_Qh[kT * kE];
__device__ __nv_bfloat16 g_Ql[kT * kE];
__device__ __nv_bfloat16 g_Kh[kT * kE];
__device__ __nv_bfloat16 g_Kl[kT * kE];
__device__ __nv_bfloat16 g_Vh[kT * kE];
__device__ __nv_bfloat16 g_Vl[kT * kE];
__device__ __nv_bfloat16 g_Ah[kT * kE];     // attention output hi/lo
__device__ __nv_bfloat16 g_Al[kT * kE];

// ---------------------------------------------------------------------------
// Helpers (plain PTX, compute_103-safe: ldmatrix + mma.sync + cp.async)
// ---------------------------------------------------------------------------
__device__ __forceinline__ uint32_t smem_u32(const void* p) {
    uint32_t a;
    asm("{ .reg .u64 t; cvta.to.shared.u64 t, %1; cvt.u32.u64 %0, t; }"
        : "=r"(a) : "l"(p));
    return a;
}

__device__ __forceinline__ void cp16(uint32_t dst, const void* src) {
    asm volatile("cp.async.cg.shared.global [%0], [%1], 16;"
                 :: "r"(dst), "l"(src) : "memory");
}
#define CP_COMMIT() asm volatile("cp.async.commit_group;" ::: "memory")
#define CP_WAIT(n)  asm volatile("cp.async.wait_group %0;" :: "n"(n) : "memory")

__device__ __forceinline__ void ldsm_x4(uint32_t& r0, uint32_t& r1,
                                        uint32_t& r2, uint32_t& r3,
                                        uint32_t addr) {
    asm volatile("ldmatrix.sync.aligned.m8n8.x4.shared.b16 {%0,%1,%2,%3}, [%4];"
                 : "=r"(r0), "=r"(r1), "=r"(r2), "=r"(r3) : "r"(addr));
}

__device__ __forceinline__ void ldsm_x4_trans(uint32_t& r0, uint32_t& r1,
                                              uint32_t& r2, uint32_t& r3,
                                              uint32_t addr) {
    asm volatile("ldmatrix.sync.aligned.m8n8.x4.trans.shared.b16 {%0,%1,%2,%3}, [%4];"
                 : "=r"(r0), "=r"(r1), "=r"(r2), "=r"(r3) : "r"(addr));
}

__device__ __forceinline__ void mma_bf16(float& d0, float& d1, float& d2, float& d3,
                                         uint32_t a0, uint32_t a1, uint32_t a2,
                                         uint32_t a3, uint32_t b0, uint32_t b1) {
    asm volatile(
        "mma.sync.aligned.m16n8k16.row.col.f32.bf16.bf16.f32 "
        "{%0,%1,%2,%3}, {%4,%5,%6,%7}, {%8,%9}, {%0,%1,%2,%3};"
        : "+f"(d0), "+f"(d1), "+f"(d2), "+f"(d3)
        : "r"(a0), "r"(a1), "r"(a2), "r"(a3), "r"(b0), "r"(b1));
}

__device__ __forceinline__ uint32_t pack_bf16(float a, float b) {
    __nv_bfloat16 ha = __float2bfloat16(a);
    __nv_bfloat16 hb = __float2bfloat16(b);
    return ((uint32_t)__bfloat16_as_ushort(hb) << 16) | __bfloat16_as_ushort(ha);
}

// ---------------------------------------------------------------------------
// Elementwise split: fp32 -> (bf16 hi, bf16 lo), lo = bf16(x - float(hi))
// ---------------------------------------------------------------------------
__global__ void split_bf16(const float* __restrict__ in,
                           __nv_bfloat16* __restrict__ hi,
                           __nv_bfloat16* __restrict__ lo, int n) {
    int i = (blockIdx.x * blockDim.x + threadIdx.x) * 4;
    if (i >= n) return;
    float4 x = *(const float4*)(in + i);
    __nv_bfloat16 h0 = __float2bfloat16(x.x);
    __nv_bfloat16 h1 = __float2bfloat16(x.y);
    __nv_bfloat16 h2 = __float2bfloat16(x.z);
    __nv_bfloat16 h3 = __float2bfloat16(x.w);
    __nv_bfloat16 l0 = __float2bfloat16(x.x - __bfloat162float(h0));
    __nv_bfloat16 l1 = __float2bfloat16(x.y - __bfloat162float(h1));
    __nv_bfloat16 l2 = __float2bfloat16(x.z - __bfloat162float(h2));
    __nv_bfloat16 l3 = __float2bfloat16(x.w - __bfloat162float(h3));
    uint2 ph, pl;
    ph.x = ((uint32_t)__bfloat16_as_ushort(h1) << 16) | __bfloat16_as_ushort(h0);
    ph.y = ((uint32_t)__bfloat16_as_ushort(h3) << 16) | __bfloat16_as_ushort(h2);
    pl.x = ((uint32_t)__bfloat16_as_ushort(l1) << 16) | __bfloat16_as_ushort(l0);
    pl.y = ((uint32_t)__bfloat16_as_ushort(l3) << 16) | __bfloat16_as_ushort(l2);
    *(uint2*)(hi + i) = ph;
    *(uint2*)(lo + i) = pl;
}

// ---------------------------------------------------------------------------
// Warp-MMA split-bf16 GEMM-NT + bias, cp.async double-buffered.
// Y[m,n] = sum_k X[m,k]*W[n,k] + b[n].  CTA 128x128, 8 warps, K-chunk 32.
// Dynamic smem: 2 stages x 4 tiles x [128 x ASTR] bf16.
// ---------------------------------------------------------------------------
#define KCH 32
#define ASTR 40                       // bf16 units per row
#define TILE_E (128 * ASTR)           // 5120 bf16 = 10240 B per tile
#define STAGE_E (4 * TILE_E)          // 20480 bf16 = 40960 B per stage
#define GEMM_SMEM (2 * STAGE_E * 2)   // 81920 B

template <bool BF16OUT>
__global__ __launch_bounds__(256, 2)
void gemm_mma_split(const __nv_bfloat16* __restrict__ Ahg,
                    const __nv_bfloat16* __restrict__ Alg,
                    const __nv_bfloat16* __restrict__ Bhg,
                    const __nv_bfloat16* __restrict__ Blg,
                    const float* __restrict__ bias,
                    float* __restrict__ Yf,
                    __nv_bfloat16* __restrict__ Yh,
                    __nv_bfloat16* __restrict__ Yl) {
    extern __shared__ __nv_bfloat16 dsm[];

    const int tid = threadIdx.x;
    const int wid = tid >> 5;
    const int lid = tid & 31;
    const int wm = (wid & 3) * 32;
    const int wn = (wid >> 2) * 64;
    const int row0 = blockIdx.y * 128;
    const int col0 = blockIdx.x * 128;

    const uint32_t ubase = smem_u32(dsm);

    // Per-thread load slots: 2 x (row, col8) covering 128x32 tile in 16B chunks
    const int r_ld[2] = {tid >> 2, (tid + 256) >> 2};
    const int c_ld[2] = {(tid & 3) * 8, ((tid + 256) & 3) * 8};

    float acc[2][8][4];
#pragma unroll
    for (int i = 0; i < 2; i++)
#pragma unroll
        for (int j = 0; j < 8; j++)
#pragma unroll
            for (int c = 0; c < 4; c++) acc[i][j][c] = 0.0f;

    const int lrow = lid & 15;
    const int lkhalf = (lid >> 4) * 8;
    const int bn = (lid >> 4) * 8 + (lid & 7);
    const int bk = ((lid >> 3) & 1) * 8;

    // ---- prefetch stage 0 ----
#pragma unroll
    for (int i = 0; i < 2; i++) {
        uint32_t so = ubase + (uint32_t)(r_ld[i] * ASTR + c_ld[i]) * 2;
        size_t ga = (size_t)(row0 + r_ld[i]) * kE + c_ld[i];
        size_t gb = (size_t)(col0 + r_ld[i]) * kE + c_ld[i];
        cp16(so, Ahg + ga);
        cp16(so + TILE_E * 2, Alg + ga);
        cp16(so + 2 * TILE_E * 2, Bhg + gb);
        cp16(so + 3 * TILE_E * 2, Blg + gb);
    }
    CP_COMMIT();

    const int NS = kE / KCH;  // 32 stages
    for (int s = 0; s < NS; s++) {
        if (s + 1 < NS) {
            int k0n = (s + 1) * KCH;
            uint32_t stb = ubase + ((s + 1) & 1) * (STAGE_E * 2);
#pragma unroll
            for (int i = 0; i < 2; i++) {
                uint32_t so = stb + (uint32_t)(r_ld[i] * ASTR + c_ld[i]) * 2;
                size_t ga = (size_t)(row0 + r_ld[i]) * kE + k0n + c_ld[i];
                size_t gb = (size_t)(col0 + r_ld[i]) * kE + k0n + c_ld[i];
                cp16(so, Ahg + ga);
                cp16(so + TILE_E * 2, Alg + ga);
                cp16(so + 2 * TILE_E * 2, Bhg + gb);
                cp16(so + 3 * TILE_E * 2, Blg + gb);
            }
            CP_COMMIT();
            CP_WAIT(1);
        } else {
            CP_WAIT(0);
        }
        __syncthreads();

        const uint32_t uAh = ubase + (s & 1) * (STAGE_E * 2);
        const uint32_t uAl = uAh + TILE_E * 2;
        const uint32_t uBh = uAh + 2 * TILE_E * 2;
        const uint32_t uBl = uAh + 3 * TILE_E * 2;

#pragma unroll
        for (int kk = 0; kk < KCH; kk += 16) {
            uint32_t ah[2][4], al[2][4];
#pragma unroll
            for (int i = 0; i < 2; i++) {
                uint32_t off = (uint32_t)((wm + i * 16 + lrow) * ASTR + kk + lkhalf) * 2;
                ldsm_x4(ah[i][0], ah[i][1], ah[i][2], ah[i][3], uAh + off);
                ldsm_x4(al[i][0], al[i][1], al[i][2], al[i][3], uAl + off);
            }
#pragma unroll
            for (int p = 0; p < 4; p++) {
                uint32_t boff = (uint32_t)((wn + p * 16 + bn) * ASTR + kk + bk) * 2;
                uint32_t bh0, bh1, bh2, bh3, bl0, bl1, bl2, bl3;
                ldsm_x4(bh0, bh1, bh2, bh3, uBh + boff);
                ldsm_x4(bl0, bl1, bl2, bl3, uBl + boff);
#pragma unroll
                for (int i = 0; i < 2; i++) {
                    float* d0 = acc[i][p * 2];
                    float* d1 = acc[i][p * 2 + 1];
                    mma_bf16(d0[0], d0[1], d0[2], d0[3],
                             ah[i][0], ah[i][1], ah[i][2], ah[i][3], bh0, bh1);
                    mma_bf16(d0[0], d0[1], d0[2], d0[3],
                             ah[i][0], ah[i][1], ah[i][2], ah[i][3], bl0, bl1);
                    mma_bf16(d0[0], d0[1], d0[2], d0[3],
                             al[i][0], al[i][1], al[i][2], al[i][3], bh0, bh1);
                    mma_bf16(d1[0], d1[1], d1[2], d1[3],
                             ah[i][0], ah[i][1], ah[i][2], ah[i][3], bh2, bh3);
                    mma_bf16(d1[0], d1[1], d1[2], d1[3],
                             ah[i][0], ah[i][1], ah[i][2], ah[i][3], bl2, bl3);
                    mma_bf16(d1[0], d1[1], d1[2], d1[3],
                             al[i][0], al[i][1], al[i][2], al[i][3], bh2, bh3);
                }
            }
        }
        __syncthreads();
    }

    const int erow = lid >> 2;
    const int ecol = (lid & 3) * 2;
#pragma unroll
    for (int i = 0; i < 2; i++) {
        int r = row0 + wm + i * 16 + erow;
#pragma unroll
        for (int j = 0; j < 8; j++) {
            int c = col0 + wn + j * 8 + ecol;
            float b0 = bias[c], b1 = bias[c + 1];
            float v00 = acc[i][j][0] + b0, v01 = acc[i][j][1] + b1;
            float v10 = acc[i][j][2] + b0, v11 = acc[i][j][3] + b1;
            if (BF16OUT) {
                __nv_bfloat16 h00 = __float2bfloat16(v00);
                __nv_bfloat16 h01 = __float2bfloat16(v01);
                __nv_bfloat16 h10 = __float2bfloat16(v10);
                __nv_bfloat16 h11 = __float2bfloat16(v11);
                uint32_t ph0 = ((uint32_t)__bfloat16_as_ushort(h01) << 16) |
                               __bfloat16_as_ushort(h00);
                uint32_t ph1 = ((uint32_t)__bfloat16_as_ushort(h11) << 16) |
                               __bfloat16_as_ushort(h10);
                uint32_t pl0 = pack_bf16(v00 - __bfloat162float(h00),
                                         v01 - __bfloat162float(h01));
                uint32_t pl1 = pack_bf16(v10 - __bfloat162float(h10),
                                         v11 - __bfloat162float(h11));
                *(uint32_t*)(Yh + (size_t)r * kE + c) = ph0;
                *(uint32_t*)(Yh + (size_t)(r + 8) * kE + c) = ph1;
                *(uint32_t*)(Yl + (size_t)r * kE + c) = pl0;
                *(uint32_t*)(Yl + (size_t)(r + 8) * kE + c) = pl1;
            } else {
                *(float2*)(Yf + (size_t)r * kE + c) = make_float2(v00, v01);
                *(float2*)(Yf + (size_t)(r + 8) * kE + c) = make_float2(v10, v11);
            }
        }
    }
}

// ---------------------------------------------------------------------------
// Varlen flash attention with mma.sync (unchanged from R4; known correct).
// ---------------------------------------------------------------------------
#define QSTR 72
#define ATTN_SMEM (27648 * 2 + 2 * 64 * 4)

__global__ __launch_bounds__(128)
void attn_mma(const __nv_bfloat16* __restrict__ Qhg,
              const __nv_bfloat16* __restrict__ Qlg,
              const __nv_bfloat16* __restrict__ Khg,
              const __nv_bfloat16* __restrict__ Klg,
              const __nv_bfloat16* __restrict__ Vhg,
              const __nv_bfloat16* __restrict__ Vlg,
              const int* __restrict__ cu,
              __nv_bfloat16* __restrict__ Oh,
              __nv_bfloat16* __restrict__ Ol) {
    extern __shared__ __nv_bfloat16 sb[];
    __nv_bfloat16* sQh = sb;
    __nv_bfloat16* sQl = sb + 4608;
    __nv_bfloat16* sKh = sb + 9216;
    __nv_bfloat16* sKl = sb + 13824;
    __nv_bfloat16* sVh = sb + 18432;
    __nv_bfloat16* sVl = sb + 23040;
    int* s_lo = (int*)(sb + 27648);
    int* s_hi = s_lo + 64;

    const int tid = threadIdx.x;
    const int wid = tid >> 5;
    const int lid = tid & 31;
    const int q0 = blockIdx.x * 64;
    const int hcol = blockIdx.y * kD;
    const int wm = wid * 16;

    const uint32_t uQh = smem_u32(sQh);
    const uint32_t uQl = smem_u32(sQl);
    const uint32_t uKh = smem_u32(sKh);
    const uint32_t uKl = smem_u32(sKl);
    const uint32_t uVh = smem_u32(sVh);
    const uint32_t uVl = smem_u32(sVl);

    if (tid < 64) {
        int r = q0 + tid;
        int lo = 0, hi = kT;
#pragma unroll
        for (int s = 0; s < 8; s++) {
            int a = cu[s], b = cu[s + 1];
            if (r >= a && r < b) { lo = a; hi = b; }
        }
        s_lo[tid] = lo;
        s_hi[tid] = hi;
    }

#pragma unroll
    for (int i = 0; i < 4; i++) {
        int f = tid + i * 128;
        int r = f >> 3;
        int c8 = (f & 7) * 8;
        size_t g = (size_t)(q0 + r) * kE + hcol + c8;
        int so = r * QSTR + c8;
        *(uint4*)(sQh + so) = *(const uint4*)(Qhg + g);
        *(uint4*)(sQl + so) = *(const uint4*)(Qlg + g);
    }
    __syncthreads();

    const int rrow = lid >> 2;
    int row_lo[2], row_hi[2];
    row_lo[0] = s_lo[wm + rrow];      row_hi[0] = s_hi[wm + rrow];
    row_lo[1] = s_lo[wm + rrow + 8];  row_hi[1] = s_hi[wm + rrow + 8];
    const int span_lo = s_lo[0];
    const int span_hi = s_hi[63];

    const int lrow = lid & 15;
    const int lkhalf = (lid >> 4) * 8;
    const int bn = (lid >> 4) * 8 + (lid & 7);
    const int bk = ((lid >> 3) & 1) * 8;
    const int vt = lid >> 3;
    const int vr = lid & 7;

    float m[2], l[2], o[8][4];
    m[0] = m[1] = -1e30f;
    l[0] = l[1] = 0.0f;
#pragma unroll
    for (int t = 0; t < 8; t++)
#pragma unroll
        for (int c = 0; c < 4; c++) o[t][c] = 0.0f;

    for (int kb = span_lo; kb < span_hi; kb += 64) {
        __syncthreads();
#pragma unroll
        for (int i = 0; i < 4; i++) {
            int f = tid + i * 128;
            int r = f >> 3;
            int c8 = (f & 7) * 8;
            int kg = kb + r;
            uint4 z = make_uint4(0, 0, 0, 0);
            uint4 vkh = z, vkl = z, vvh = z, vvl = z;
            if (kg < span_hi) {
                size_t g = (size_t)kg * kE + hcol + c8;
                vkh = *(const uint4*)(Khg + g);
                vkl = *(const uint4*)(Klg + g);
                vvh = *(const uint4*)(Vhg + g);
                vvl = *(const uint4*)(Vlg + g);
            }
            int so = r * QSTR + c8;
            *(uint4*)(sKh + so) = vkh;
            *(uint4*)(sKl + so) = vkl;
            *(uint4*)(sVh + so) = vvh;
            *(uint4*)(sVl + so) = vvl;
        }
        __syncthreads();

        float s[8][4];
#pragma unroll
        for (int t = 0; t < 8; t++)
#pragma unroll
            for (int c = 0; c < 4; c++) s[t][c] = 0.0f;

#pragma unroll
        for (int kc = 0; kc < 4; kc++) {
            uint32_t qh[4], ql[4];
            uint32_t aoff = (uint32_t)((wm + lrow) * QSTR + kc * 16 + lkhalf) * 2;
            ldsm_x4(qh[0], qh[1], qh[2], qh[3], uQh + aoff);
            ldsm_x4(ql[0], ql[1], ql[2], ql[3], uQl + aoff);
#pragma unroll
            for (int p = 0; p < 4; p++) {
                uint32_t boff = (uint32_t)((p * 16 + bn) * QSTR + kc * 16 + bk) * 2;
                uint32_t kh0, kh1, kh2, kh3, kl0, kl1, kl2, kl3;
                ldsm_x4(kh0, kh1, kh2, kh3, uKh + boff);
                ldsm_x4(kl0, kl1, kl2, kl3, uKl + boff);
                float* d0 = s[p * 2];
                float* d1 = s[p * 2 + 1];
                mma_bf16(d0[0], d0[1], d0[2], d0[3], qh[0], qh[1], qh[2], qh[3], kh0, kh1);
                mma_bf16(d0[0], d0[1], d0[2], d0[3], qh[0], qh[1], qh[2], qh[3], kl0, kl1);
                mma_bf16(d0[0], d0[1], d0[2], d0[3], ql[0], ql[1], ql[2], ql[3], kh0, kh1);
                mma_bf16(d1[0], d1[1], d1[2], d1[3], qh[0], qh[1], qh[2], qh[3], kh2, kh3);
                mma_bf16(d1[0], d1[1], d1[2], d1[3], qh[0], qh[1], qh[2], qh[3], kl2, kl3);
                mma_bf16(d1[0], d1[1], d1[2], d1[3], ql[0], ql[1], ql[2], ql[3], kh2, kh3);
            }
        }

        const int colb = (lid & 3) * 2;
#pragma unroll
        for (int i = 0; i < 2; i++) {
            float rm = -1e30f;
#pragma unroll
            for (int t = 0; t < 8; t++) {
                int kg0 = kb + t * 8 + colb;
                float v0 = s[t][2 * i] * 0.125f;
                float v1 = s[t][2 * i + 1] * 0.125f;
                if (kg0 < row_lo[i] || kg0 >= row_hi[i]) v0 = -1e30f;
                if (kg0 + 1 < row_lo[i] || kg0 + 1 >= row_hi[i]) v1 = -1e30f;
                s[t][2 * i] = v0;
                s[t][2 * i + 1] = v1;
                rm = fmaxf(rm, fmaxf(v0, v1));
            }
            rm = fmaxf(rm, __shfl_xor_sync(0xffffffffu, rm, 1));
            rm = fmaxf(rm, __shfl_xor_sync(0xffffffffu, rm, 2));

            float mn = fmaxf(m[i], rm);
            float c = __expf(m[i] - mn);
            float rs = 0.0f;
#pragma unroll
            for (int t = 0; t < 8; t++) {
                float v0 = s[t][2 * i];
                float v1 = s[t][2 * i + 1];
                float p0 = (v0 <= -1e29f) ? 0.0f : __expf(v0 - mn);
                float p1 = (v1 <= -1e29f) ? 0.0f : __expf(v1 - mn);
                s[t][2 * i] = p0;
                s[t][2 * i + 1] = p1;
                rs += p0 + p1;
            }
            rs += __shfl_xor_sync(0xffffffffu, rs, 1);
            rs += __shfl_xor_sync(0xffffffffu, rs, 2);

            l[i] = l[i] * c + rs;
            m[i] = mn;
#pragma unroll
            for (int t = 0; t < 8; t++) {
                o[t][2 * i] *= c;
                o[t][2 * i + 1] *= c;
            }
        }

#pragma unroll
        for (int kc = 0; kc < 4; kc++) {
            int t0 = 2 * kc, t1 = 2 * kc + 1;
            uint32_t ph[4], pl[4];
            {
                __nv_bfloat16 h;
                float f0, f1;
                f0 = s[t0][0]; f1 = s[t0][1];
                ph[0] = pack_bf16(f0, f1);
                h = __float2bfloat16(f0); f0 -= __bfloat162float(h);
                h = __float2bfloat16(f1); f1 -= __bfloat162float(h);
                pl[0] = pack_bf16(f0, f1);
                f0 = s[t0][2]; f1 = s[t0][3];
                ph[1] = pack_bf16(f0, f1);
                h = __float2bfloat16(f0); f0 -= __bfloat162float(h);
                h = __float2bfloat16(f1); f1 -= __bfloat162float(h);
                pl[1] = pack_bf16(f0, f1);
                f0 = s[t1][0]; f1 = s[t1][1];
                ph[2] = pack_bf16(f0, f1);
                h = __float2bfloat16(f0); f0 -= __bfloat162float(h);
                h = __float2bfloat16(f1); f1 -= __bfloat162float(h);
                pl[2] = pack_bf16(f0, f1);
                f0 = s[t1][2]; f1 = s[t1][3];
                ph[3] = pack_bf16(f0, f1);
                h = __float2bfloat16(f0); f0 -= __bfloat162float(h);
                h = __float2bfloat16(f1); f1 -= __bfloat162float(h);
                pl[3] = pack_bf16(f0, f1);
            }
#pragma unroll
            for (int dp = 0; dp < 4; dp++) {
                uint32_t voff = (uint32_t)((kc * 16 + (vt & 1) * 8 + vr) * QSTR +
                                           dp * 16 + (vt >> 1) * 8) * 2;
                uint32_t vh0, vh1, vh2, vh3, vl0, vl1, vl2, vl3;
                ldsm_x4_trans(vh0, vh1, vh2, vh3, uVh + voff);
                ldsm_x4_trans(vl0, vl1, vl2, vl3, uVl + voff);
                float* d0 = o[dp * 2];
                float* d1 = o[dp * 2 + 1];
                mma_bf16(d0[0], d0[1], d0[2], d0[3], ph[0], ph[1], ph[2], ph[3], vh0, vh1);
                mma_bf16(d0[0], d0[1], d0[2], d0[3], ph[0], ph[1], ph[2], ph[3], vl0, vl1);
                mma_bf16(d0[0], d0[1], d0[2], d0[3], pl[0], pl[1], pl[2], pl[3], vh0, vh1);
                mma_bf16(d1[0], d1[1], d1[2], d1[3], ph[0], ph[1], ph[2], ph[3], vh2, vh3);
                mma_bf16(d1[0], d1[1], d1[2], d1[3], ph[0], ph[1], ph[2], ph[3], vl2, vl3);
                mma_bf16(d1[0], d1[1], d1[2], d1[3], pl[0], pl[1], pl[2], pl[3], vh2, vh3);
            }
        }
    }

    float inv0 = 1.0f / l[0];
    float inv1 = 1.0f / l[1];
    const int colb = (lid & 3) * 2;
#pragma unroll
    for (int t = 0; t < 8; t++) {
        int col = hcol + t * 8 + colb;
        int r0 = q0 + wm + rrow;
        float v00 = o[t][0] * inv0, v01 = o[t][1] * inv0;
        float v10 = o[t][2] * inv1, v11 = o[t][3] * inv1;
        __nv_bfloat16 h00 = __float2bfloat16(v00);
        __nv_bfloat16 h01 = __float2bfloat16(v01);
        __nv_bfloat16 h10 = __float2bfloat16(v10);
        __nv_bfloat16 h11 = __float2bfloat16(v11);
        uint32_t ph0 = ((uint32_t)__bfloat16_as_ushort(h01) << 16) |
                       __bfloat16_as_ushort(h00);
        uint32_t ph1 = ((uint32_t)__bfloat16_as_ushort(h11) << 16) |
                       __bfloat16_as_ushort(h10);
        uint32_t pl0 = pack_bf16(v00 - __bfloat162float(h00),
                                 v01 - __bfloat162float(h01));
        uint32_t pl1 = pack_bf16(v10 - __bfloat162float(h10),
                                 v11 - __bfloat162float(h11));
        *(uint32_t*)(Oh + (size_t)r0 * kE + col) = ph0;
        *(uint32_t*)(Oh + (size_t)(r0 + 8) * kE + col) = ph1;
        *(uint32_t*)(Ol + (size_t)r0 * kE + col) = pl0;
        *(uint32_t*)(Ol + (size_t)(r0 + 8) * kE + col) = pl1;
    }
}

// ---------------------------------------------------------------------------
extern "C" void kernel_launch(void* const* d_in, const int* in_sizes, int n_in,
                              void* d_out, int out_size) {
    const float* hs = (const float*)d_in[0];
    const int* cu   = (const int*)d_in[1];
    const float* W[4] = {(const float*)d_in[2], (const float*)d_in[4],
                         (const float*)d_in[6], (const float*)d_in[8]};
    const float* b[4] = {(const float*)d_in[3], (const float*)d_in[5],
                         (const float*)d_in[7], (const float*)d_in[9]};
    float* out = (float*)d_out;

    __nv_bfloat16 *Xh, *Xl, *Wh, *Wl, *Qh, *Ql, *Kh, *Kl, *Vh, *Vl, *Ah, *Al;
    cudaGetSymbolAddress((void**)&Xh, g_Xh);
    cudaGetSymbolAddress((void**)&Xl, g_Xl);
    cudaGetSymbolAddress((void**)&Wh, g_Wh);
    cudaGetSymbolAddress((void**)&Wl, g_Wl);
    cudaGetSymbolAddress((void**)&Qh, g_Qh);
    cudaGetSymbolAddress((void**)&Ql, g_Ql);
    cudaGetSymbolAddress((void**)&Kh, g_Kh);
    cudaGetSymbolAddress((void**)&Kl, g_Kl);
    cudaGetSymbolAddress((void**)&Vh, g_Vh);
    cudaGetSymbolAddress((void**)&Vl, g_Vl);
    cudaGetSymbolAddress((void**)&Ah, g_Ah);
    cudaGetSymbolAddress((void**)&Al, g_Al);

    cudaFuncSetAttribute(attn_mma,
                         cudaFuncAttributeMaxDynamicSharedMemorySize, ATTN_SMEM);
    cudaFuncSetAttribute(gemm_mma_split<true>,
                         cudaFuncAttributeMaxDynamicSharedMemorySize, GEMM_SMEM);
    cudaFuncSetAttribute(gemm_mma_split<false>,
                         cudaFuncAttributeMaxDynamicSharedMemorySize, GEMM_SMEM);

    const int nX = kT * kE;
    const int nW = kE * kE;

    split_bf16<<<nX / 4 / 256, 256>>>(hs, Xh, Xl, nX);
    for (int i = 0; i < 4; i++)
        split_bf16<<<nW / 4 / 256, 256>>>(W[i], Wh + (size_t)i * nW,
                                          Wl + (size_t)i * nW, nW);

    dim3 ggrid(kE / 128, kT / 128);  // (8, 32)
    gemm_mma_split<true><<<ggrid, 256, GEMM_SMEM>>>(Xh, Xl, Wh + 0 * (size_t)nW,
                                                    Wl + 0 * (size_t)nW, b[0],
                                                    nullptr, Qh, Ql);
    gemm_mma_split<true><<<ggrid, 256, GEMM_SMEM>>>(Xh, Xl, Wh + 1 * (size_t)nW,
                                                    Wl + 1 * (size_t)nW, b[1],
                                                    nullptr, Kh, Kl);
    gemm_mma_split<true><<<ggrid, 256, GEMM_SMEM>>>(Xh, Xl, Wh + 2 * (size_t)nW,
                                                    Wl + 2 * (size_t)nW, b[2],
                                                    nullptr, Vh, Vl);

    attn_mma<<<dim3(kT / 64, kH), 128, ATTN_SMEM>>>(Qh, Ql, Kh, Kl, Vh, Vl,
                                                    cu, Ah, Al);

    gemm_mma_split<false><<<ggrid, 256, GEMM_SMEM>>>(Ah, Al, Wh + 3 * (size_t)nW,
                                                     Wl + 3 * (size_t)nW, b[3],
                                                     out, nullptr, nullptr);
}

// round 6
// speedup vs baseline: 1.4531x; 1.4531x over previous
#include <cuda_runtime.h>
#include <cuda_fp16.h>
#include <math.h>
#include <cstdint>

// Problem constants
#define kT 4096
#define kE 1024
#define kH 16
#define kD 64

// ---------------------------------------------------------------------------
// Scratch (__device__ globals; allocation-free rule)
// A-side operands need hi+lo (corrected); B-side operands need hi only.
// ---------------------------------------------------------------------------
__device__ __half g_Xh[kT * kE];
__device__ __half g_Xl[kT * kE];
__device__ __half g_Wh[4][kE * kE];   // q,k,v,o weights, hi only
__device__ __half g_Qh[kT * kE];
__device__ __half g_Ql[kT * kE];
__device__ __half g_Kh[kT * kE];      // K: B-side of S -> hi only
__device__ __half g_Vh[kT * kE];      // V: B-side of PV -> hi only
__device__ __half g_Ah[kT * kE];      // attention out hi/lo (A-side of O-proj)
__device__ __half g_Al[kT * kE];

// ---------------------------------------------------------------------------
// Helpers (plain PTX, compute_103-safe)
// ---------------------------------------------------------------------------
__device__ __forceinline__ uint32_t smem_u32(const void* p) {
    uint32_t a;
    asm("{ .reg .u64 t; cvta.to.shared.u64 t, %1; cvt.u32.u64 %0, t; }"
        : "=r"(a) : "l"(p));
    return a;
}

__device__ __forceinline__ void cp16(uint32_t dst, const void* src) {
    asm volatile("cp.async.cg.shared.global [%0], [%1], 16;"
                 :: "r"(dst), "l"(src) : "memory");
}
#define CP_COMMIT() asm volatile("cp.async.commit_group;" ::: "memory")
#define CP_WAIT(n)  asm volatile("cp.async.wait_group %0;" :: "n"(n) : "memory")

__device__ __forceinline__ void ldsm_x4(uint32_t& r0, uint32_t& r1,
                                        uint32_t& r2, uint32_t& r3,
                                        uint32_t addr) {
    asm volatile("ldmatrix.sync.aligned.m8n8.x4.shared.b16 {%0,%1,%2,%3}, [%4];"
                 : "=r"(r0), "=r"(r1), "=r"(r2), "=r"(r3) : "r"(addr));
}

__device__ __forceinline__ void ldsm_x4_trans(uint32_t& r0, uint32_t& r1,
                                              uint32_t& r2, uint32_t& r3,
                                              uint32_t addr) {
    asm volatile("ldmatrix.sync.aligned.m8n8.x4.trans.shared.b16 {%0,%1,%2,%3}, [%4];"
                 : "=r"(r0), "=r"(r1), "=r"(r2), "=r"(r3) : "r"(addr));
}

__device__ __forceinline__ void mma_f16(float& d0, float& d1, float& d2, float& d3,
                                        uint32_t a0, uint32_t a1, uint32_t a2,
                                        uint32_t a3, uint32_t b0, uint32_t b1) {
    asm volatile(
        "mma.sync.aligned.m16n8k16.row.col.f32.f16.f16.f32 "
        "{%0,%1,%2,%3}, {%4,%5,%6,%7}, {%8,%9}, {%0,%1,%2,%3};"
        : "+f"(d0), "+f"(d1), "+f"(d2), "+f"(d3)
        : "r"(a0), "r"(a1), "r"(a2), "r"(a3), "r"(b0), "r"(b1));
}

__device__ __forceinline__ uint32_t pack_f16(float a, float b) {
    __half ha = __float2half_rn(a);
    __half hb = __float2half_rn(b);
    return ((uint32_t)__half_as_ushort(hb) << 16) | __half_as_ushort(ha);
}

// ---------------------------------------------------------------------------
// Elementwise: fp32 -> (fp16 hi, fp16 lo), lo = f16(x - float(hi))
// ---------------------------------------------------------------------------
__global__ void split_f16(const float* __restrict__ in,
                          __half* __restrict__ hi,
                          __half* __restrict__ lo, int n) {
    int i = (blockIdx.x * blockDim.x + threadIdx.x) * 4;
    if (i >= n) return;
    float4 x = *(const float4*)(in + i);
    __half h0 = __float2half_rn(x.x);
    __half h1 = __float2half_rn(x.y);
    __half h2 = __float2half_rn(x.z);
    __half h3 = __float2half_rn(x.w);
    uint2 ph, pl;
    ph.x = ((uint32_t)__half_as_ushort(h1) << 16) | __half_as_ushort(h0);
    ph.y = ((uint32_t)__half_as_ushort(h3) << 16) | __half_as_ushort(h2);
    pl.x = pack_f16(x.x - __half2float(h0), x.y - __half2float(h1));
    pl.y = pack_f16(x.z - __half2float(h2), x.w - __half2float(h3));
    *(uint2*)(hi + i) = ph;
    *(uint2*)(lo + i) = pl;
}

// fp32 -> fp16 hi only (for weights / B-side operands)
__global__ void cvt_f16(const float* __restrict__ in,
                        __half* __restrict__ hi, int n) {
    int i = (blockIdx.x * blockDim.x + threadIdx.x) * 4;
    if (i >= n) return;
    float4 x = *(const float4*)(in + i);
    uint2 ph;
    ph.x = pack_f16(x.x, x.y);
    ph.y = pack_f16(x.z, x.w);
    *(uint2*)(hi + i) = ph;
}

// ---------------------------------------------------------------------------
// Warp-MMA fp16 2-term GEMM-NT + bias, cp.async double-buffered.
// Y[m,n] = sum_k X[m,k]*W[n,k] + b[n].  CTA 128x128, 8 warps, K-chunk 32.
// D = Ah*Bh + Al*Bh  (A-side corrected; B residual ~1.6e-4 RMS).
// OUTMODE: 0 = fp32, 1 = fp16 hi only, 2 = fp16 hi+lo.
// ---------------------------------------------------------------------------
#define KCH 32
#define ASTR 40                       // fp16 units per row
#define TILE_E (128 * ASTR)           // 5120 halfs = 10240 B per tile
#define STAGE_E (3 * TILE_E)          // Ah, Al, Bh
#define GEMM_SMEM (2 * STAGE_E * 2)   // 61440 B

template <int OUTMODE>
__global__ __launch_bounds__(256, 2)
void gemm_mma_f16(const __half* __restrict__ Ahg,
                  const __half* __restrict__ Alg,
                  const __half* __restrict__ Bhg,
                  const float* __restrict__ bias,
                  float* __restrict__ Yf,
                  __half* __restrict__ Yh,
                  __half* __restrict__ Yl) {
    extern __shared__ __half dsm[];

    const int tid = threadIdx.x;
    const int wid = tid >> 5;
    const int lid = tid & 31;
    const int wm = (wid & 3) * 32;
    const int wn = (wid >> 2) * 64;
    const int row0 = blockIdx.y * 128;
    const int col0 = blockIdx.x * 128;

    const uint32_t ubase = smem_u32(dsm);

    const int r_ld[2] = {tid >> 2, (tid + 256) >> 2};
    const int c_ld[2] = {(tid & 3) * 8, ((tid + 256) & 3) * 8};

    float acc[2][8][4];
#pragma unroll
    for (int i = 0; i < 2; i++)
#pragma unroll
        for (int j = 0; j < 8; j++)
#pragma unroll
            for (int c = 0; c < 4; c++) acc[i][j][c] = 0.0f;

    const int lrow = lid & 15;
    const int lkhalf = (lid >> 4) * 8;
    const int bn = (lid >> 4) * 8 + (lid & 7);
    const int bk = ((lid >> 3) & 1) * 8;

    // prefetch stage 0
#pragma unroll
    for (int i = 0; i < 2; i++) {
        uint32_t so = ubase + (uint32_t)(r_ld[i] * ASTR + c_ld[i]) * 2;
        size_t ga = (size_t)(row0 + r_ld[i]) * kE + c_ld[i];
        size_t gb = (size_t)(col0 + r_ld[i]) * kE + c_ld[i];
        cp16(so, Ahg + ga);
        cp16(so + TILE_E * 2, Alg + ga);
        cp16(so + 2 * TILE_E * 2, Bhg + gb);
    }
    CP_COMMIT();

    const int NS = kE / KCH;
    for (int s = 0; s < NS; s++) {
        if (s + 1 < NS) {
            int k0n = (s + 1) * KCH;
            uint32_t stb = ubase + ((s + 1) & 1) * (STAGE_E * 2);
#pragma unroll
            for (int i = 0; i < 2; i++) {
                uint32_t so = stb + (uint32_t)(r_ld[i] * ASTR + c_ld[i]) * 2;
                size_t ga = (size_t)(row0 + r_ld[i]) * kE + k0n + c_ld[i];
                size_t gb = (size_t)(col0 + r_ld[i]) * kE + k0n + c_ld[i];
                cp16(so, Ahg + ga);
                cp16(so + TILE_E * 2, Alg + ga);
                cp16(so + 2 * TILE_E * 2, Bhg + gb);
            }
            CP_COMMIT();
            CP_WAIT(1);
        } else {
            CP_WAIT(0);
        }
        __syncthreads();

        const uint32_t uAh = ubase + (s & 1) * (STAGE_E * 2);
        const uint32_t uAl = uAh + TILE_E * 2;
        const uint32_t uBh = uAh + 2 * TILE_E * 2;

#pragma unroll
        for (int kk = 0; kk < KCH; kk += 16) {
            uint32_t ah[2][4], al[2][4];
#pragma unroll
            for (int i = 0; i < 2; i++) {
                uint32_t off = (uint32_t)((wm + i * 16 + lrow) * ASTR + kk + lkhalf) * 2;
                ldsm_x4(ah[i][0], ah[i][1], ah[i][2], ah[i][3], uAh + off);
                ldsm_x4(al[i][0], al[i][1], al[i][2], al[i][3], uAl + off);
            }
#pragma unroll
            for (int p = 0; p < 4; p++) {
                uint32_t boff = (uint32_t)((wn + p * 16 + bn) * ASTR + kk + bk) * 2;
                uint32_t bh0, bh1, bh2, bh3;
                ldsm_x4(bh0, bh1, bh2, bh3, uBh + boff);
#pragma unroll
                for (int i = 0; i < 2; i++) {
                    float* d0 = acc[i][p * 2];
                    float* d1 = acc[i][p * 2 + 1];
                    mma_f16(d0[0], d0[1], d0[2], d0[3],
                            ah[i][0], ah[i][1], ah[i][2], ah[i][3], bh0, bh1);
                    mma_f16(d0[0], d0[1], d0[2], d0[3],
                            al[i][0], al[i][1], al[i][2], al[i][3], bh0, bh1);
                    mma_f16(d1[0], d1[1], d1[2], d1[3],
                            ah[i][0], ah[i][1], ah[i][2], ah[i][3], bh2, bh3);
                    mma_f16(d1[0], d1[1], d1[2], d1[3],
                            al[i][0], al[i][1], al[i][2], al[i][3], bh2, bh3);
                }
            }
        }
        __syncthreads();
    }

    const int erow = lid >> 2;
    const int ecol = (lid & 3) * 2;
#pragma unroll
    for (int i = 0; i < 2; i++) {
        int r = row0 + wm + i * 16 + erow;
#pragma unroll
        for (int j = 0; j < 8; j++) {
            int c = col0 + wn + j * 8 + ecol;
            float b0 = bias[c], b1 = bias[c + 1];
            float v00 = acc[i][j][0] + b0, v01 = acc[i][j][1] + b1;
            float v10 = acc[i][j][2] + b0, v11 = acc[i][j][3] + b1;
            if (OUTMODE == 0) {
                *(float2*)(Yf + (size_t)r * kE + c) = make_float2(v00, v01);
                *(float2*)(Yf + (size_t)(r + 8) * kE + c) = make_float2(v10, v11);
            } else {
                __half h00 = __float2half_rn(v00);
                __half h01 = __float2half_rn(v01);
                __half h10 = __float2half_rn(v10);
                __half h11 = __float2half_rn(v11);
                uint32_t ph0 = ((uint32_t)__half_as_ushort(h01) << 16) |
                               __half_as_ushort(h00);
                uint32_t ph1 = ((uint32_t)__half_as_ushort(h11) << 16) |
                               __half_as_ushort(h10);
                *(uint32_t*)(Yh + (size_t)r * kE + c) = ph0;
                *(uint32_t*)(Yh + (size_t)(r + 8) * kE + c) = ph1;
                if (OUTMODE == 2) {
                    uint32_t pl0 = pack_f16(v00 - __half2float(h00),
                                            v01 - __half2float(h01));
                    uint32_t pl1 = pack_f16(v10 - __half2float(h10),
                                            v11 - __half2float(h11));
                    *(uint32_t*)(Yl + (size_t)r * kE + c) = pl0;
                    *(uint32_t*)(Yl + (size_t)(r + 8) * kE + c) = pl1;
                }
            }
        }
    }
}

// ---------------------------------------------------------------------------
// Varlen flash attention, fp16 2-term mma.
// S = Qh*Kh + Ql*Kh;  O += Ph*Vh + Pl*Vh.
// Grid (kT/64, kH), 128 threads (4 warps), warp w -> q rows w*16..+16.
// ---------------------------------------------------------------------------
#define QSTR 72
// halfs: Qh 0, Ql 4608, Kh 9216, Vh 13824, end 18432
#define ATTN_SMEM (18432 * 2 + 2 * 64 * 4)

__global__ __launch_bounds__(128)
void attn_mma(const __half* __restrict__ Qhg,
              const __half* __restrict__ Qlg,
              const __half* __restrict__ Khg,
              const __half* __restrict__ Vhg,
              const int* __restrict__ cu,
              __half* __restrict__ Oh,
              __half* __restrict__ Ol) {
    extern __shared__ __half sb[];
    __half* sQh = sb;
    __half* sQl = sb + 4608;
    __half* sKh = sb + 9216;
    __half* sVh = sb + 13824;
    int* s_lo = (int*)(sb + 18432);
    int* s_hi = s_lo + 64;

    const int tid = threadIdx.x;
    const int wid = tid >> 5;
    const int lid = tid & 31;
    const int q0 = blockIdx.x * 64;
    const int hcol = blockIdx.y * kD;
    const int wm = wid * 16;

    const uint32_t uQh = smem_u32(sQh);
    const uint32_t uQl = smem_u32(sQl);
    const uint32_t uKh = smem_u32(sKh);
    const uint32_t uVh = smem_u32(sVh);

    if (tid < 64) {
        int r = q0 + tid;
        int lo = 0, hi = kT;
#pragma unroll
        for (int s = 0; s < 8; s++) {
            int a = cu[s], b = cu[s + 1];
            if (r >= a && r < b) { lo = a; hi = b; }
        }
        s_lo[tid] = lo;
        s_hi[tid] = hi;
    }

#pragma unroll
    for (int i = 0; i < 4; i++) {
        int f = tid + i * 128;
        int r = f >> 3;
        int c8 = (f & 7) * 8;
        size_t g = (size_t)(q0 + r) * kE + hcol + c8;
        int so = r * QSTR + c8;
        *(uint4*)(sQh + so) = *(const uint4*)(Qhg + g);
        *(uint4*)(sQl + so) = *(const uint4*)(Qlg + g);
    }
    __syncthreads();

    const int rrow = lid >> 2;
    int row_lo[2], row_hi[2];
    row_lo[0] = s_lo[wm + rrow];      row_hi[0] = s_hi[wm + rrow];
    row_lo[1] = s_lo[wm + rrow + 8];  row_hi[1] = s_hi[wm + rrow + 8];
    const int span_lo = s_lo[0];
    const int span_hi = s_hi[63];

    const int lrow = lid & 15;
    const int lkhalf = (lid >> 4) * 8;
    const int bn = (lid >> 4) * 8 + (lid & 7);
    const int bk = ((lid >> 3) & 1) * 8;
    const int vt = lid >> 3;
    const int vr = lid & 7;

    float m[2], l[2], o[8][4];
    m[0] = m[1] = -1e30f;
    l[0] = l[1] = 0.0f;
#pragma unroll
    for (int t = 0; t < 8; t++)
#pragma unroll
        for (int c = 0; c < 4; c++) o[t][c] = 0.0f;

    for (int kb = span_lo; kb < span_hi; kb += 64) {
        __syncthreads();
        // Load K, V hi tiles (zero-fill beyond span_hi): 2 uint4/thread each
#pragma unroll
        for (int i = 0; i < 4; i++) {
            int f = tid + i * 128;
            int r = f >> 3;
            int c8 = (f & 7) * 8;
            int kg = kb + r;
            uint4 z = make_uint4(0, 0, 0, 0);
            uint4 vkh = z, vvh = z;
            if (kg < span_hi) {
                size_t g = (size_t)kg * kE + hcol + c8;
                vkh = *(const uint4*)(Khg + g);
                vvh = *(const uint4*)(Vhg + g);
            }
            int so = r * QSTR + c8;
            *(uint4*)(sKh + so) = vkh;
            *(uint4*)(sVh + so) = vvh;
        }
        __syncthreads();

        float s[8][4];
#pragma unroll
        for (int t = 0; t < 8; t++)
#pragma unroll
            for (int c = 0; c < 4; c++) s[t][c] = 0.0f;

#pragma unroll
        for (int kc = 0; kc < 4; kc++) {
            uint32_t qh[4], ql[4];
            uint32_t aoff = (uint32_t)((wm + lrow) * QSTR + kc * 16 + lkhalf) * 2;
            ldsm_x4(qh[0], qh[1], qh[2], qh[3], uQh + aoff);
            ldsm_x4(ql[0], ql[1], ql[2], ql[3], uQl + aoff);
#pragma unroll
            for (int p = 0; p < 4; p++) {
                uint32_t boff = (uint32_t)((p * 16 + bn) * QSTR + kc * 16 + bk) * 2;
                uint32_t kh0, kh1, kh2, kh3;
                ldsm_x4(kh0, kh1, kh2, kh3, uKh + boff);
                float* d0 = s[p * 2];
                float* d1 = s[p * 2 + 1];
                mma_f16(d0[0], d0[1], d0[2], d0[3], qh[0], qh[1], qh[2], qh[3], kh0, kh1);
                mma_f16(d0[0], d0[1], d0[2], d0[3], ql[0], ql[1], ql[2], ql[3], kh0, kh1);
                mma_f16(d1[0], d1[1], d1[2], d1[3], qh[0], qh[1], qh[2], qh[3], kh2, kh3);
                mma_f16(d1[0], d1[1], d1[2], d1[3], ql[0], ql[1], ql[2], ql[3], kh2, kh3);
            }
        }

        const int colb = (lid & 3) * 2;
#pragma unroll
        for (int i = 0; i < 2; i++) {
            float rm = -1e30f;
#pragma unroll
            for (int t = 0; t < 8; t++) {
                int kg0 = kb + t * 8 + colb;
                float v0 = s[t][2 * i] * 0.125f;
                float v1 = s[t][2 * i + 1] * 0.125f;
                if (kg0 < row_lo[i] || kg0 >= row_hi[i]) v0 = -1e30f;
                if (kg0 + 1 < row_lo[i] || kg0 + 1 >= row_hi[i]) v1 = -1e30f;
                s[t][2 * i] = v0;
                s[t][2 * i + 1] = v1;
                rm = fmaxf(rm, fmaxf(v0, v1));
            }
            rm = fmaxf(rm, __shfl_xor_sync(0xffffffffu, rm, 1));
            rm = fmaxf(rm, __shfl_xor_sync(0xffffffffu, rm, 2));

            float mn = fmaxf(m[i], rm);
            float c = __expf(m[i] - mn);
            float rs = 0.0f;
#pragma unroll
            for (int t = 0; t < 8; t++) {
                float v0 = s[t][2 * i];
                float v1 = s[t][2 * i + 1];
                float p0 = (v0 <= -1e29f) ? 0.0f : __expf(v0 - mn);
                float p1 = (v1 <= -1e29f) ? 0.0f : __expf(v1 - mn);
                s[t][2 * i] = p0;
                s[t][2 * i + 1] = p1;
                rs += p0 + p1;
            }
            rs += __shfl_xor_sync(0xffffffffu, rs, 1);
            rs += __shfl_xor_sync(0xffffffffu, rs, 2);

            l[i] = l[i] * c + rs;
            m[i] = mn;
#pragma unroll
            for (int t = 0; t < 8; t++) {
                o[t][2 * i] *= c;
                o[t][2 * i + 1] *= c;
            }
        }

        // O += P V (P split hi/lo in regs, V hi only)
#pragma unroll
        for (int kc = 0; kc < 4; kc++) {
            int t0 = 2 * kc, t1 = 2 * kc + 1;
            uint32_t ph[4], pl[4];
            {
                __half h0, h1;
                float f0, f1;
                f0 = s[t0][0]; f1 = s[t0][1];
                h0 = __float2half_rn(f0); h1 = __float2half_rn(f1);
                ph[0] = ((uint32_t)__half_as_ushort(h1) << 16) | __half_as_ushort(h0);
                pl[0] = pack_f16(f0 - __half2float(h0), f1 - __half2float(h1));
                f0 = s[t0][2]; f1 = s[t0][3];
                h0 = __float2half_rn(f0); h1 = __float2half_rn(f1);
                ph[1] = ((uint32_t)__half_as_ushort(h1) << 16) | __half_as_ushort(h0);
                pl[1] = pack_f16(f0 - __half2float(h0), f1 - __half2float(h1));
                f0 = s[t1][0]; f1 = s[t1][1];
                h0 = __float2half_rn(f0); h1 = __float2half_rn(f1);
                ph[2] = ((uint32_t)__half_as_ushort(h1) << 16) | __half_as_ushort(h0);
                pl[2] = pack_f16(f0 - __half2float(h0), f1 - __half2float(h1));
                f0 = s[t1][2]; f1 = s[t1][3];
                h0 = __float2half_rn(f0); h1 = __float2half_rn(f1);
                ph[3] = ((uint32_t)__half_as_ushort(h1) << 16) | __half_as_ushort(h0);
                pl[3] = pack_f16(f0 - __half2float(h0), f1 - __half2float(h1));
            }
#pragma unroll
            for (int dp = 0; dp < 4; dp++) {
                uint32_t voff = (uint32_t)((kc * 16 + (vt & 1) * 8 + vr) * QSTR +
                                           dp * 16 + (vt >> 1) * 8) * 2;
                uint32_t vh0, vh1, vh2, vh3;
                ldsm_x4_trans(vh0, vh1, vh2, vh3, uVh + voff);
                float* d0 = o[dp * 2];
                float* d1 = o[dp * 2 + 1];
                mma_f16(d0[0], d0[1], d0[2], d0[3], ph[0], ph[1], ph[2], ph[3], vh0, vh1);
                mma_f16(d0[0], d0[1], d0[2], d0[3], pl[0], pl[1], pl[2], pl[3], vh0, vh1);
                mma_f16(d1[0], d1[1], d1[2], d1[3], ph[0], ph[1], ph[2], ph[3], vh2, vh3);
                mma_f16(d1[0], d1[1], d1[2], d1[3], pl[0], pl[1], pl[2], pl[3], vh2, vh3);
            }
        }
    }

    float inv0 = 1.0f / l[0];
    float inv1 = 1.0f / l[1];
    const int colb = (lid & 3) * 2;
#pragma unroll
    for (int t = 0; t < 8; t++) {
        int col = hcol + t * 8 + colb;
        int r0 = q0 + wm + rrow;
        float v00 = o[t][0] * inv0, v01 = o[t][1] * inv0;
        float v10 = o[t][2] * inv1, v11 = o[t][3] * inv1;
        __half h00 = __float2half_rn(v00);
        __half h01 = __float2half_rn(v01);
        __half h10 = __float2half_rn(v10);
        __half h11 = __float2half_rn(v11);
        uint32_t ph0 = ((uint32_t)__half_as_ushort(h01) << 16) | __half_as_ushort(h00);
        uint32_t ph1 = ((uint32_t)__half_as_ushort(h11) << 16) | __half_as_ushort(h10);
        uint32_t pl0 = pack_f16(v00 - __half2float(h00), v01 - __half2float(h01));
        uint32_t pl1 = pack_f16(v10 - __half2float(h10), v11 - __half2float(h11));
        *(uint32_t*)(Oh + (size_t)r0 * kE + col) = ph0;
        *(uint32_t*)(Oh + (size_t)(r0 + 8) * kE + col) = ph1;
        *(uint32_t*)(Ol + (size_t)r0 * kE + col) = pl0;
        *(uint32_t*)(Ol + (size_t)(r0 + 8) * kE + col) = pl1;
    }
}

// ---------------------------------------------------------------------------
extern "C" void kernel_launch(void* const* d_in, const int* in_sizes, int n_in,
                              void* d_out, int out_size) {
    const float* hs = (const float*)d_in[0];
    const int* cu   = (const int*)d_in[1];
    const float* W[4] = {(const float*)d_in[2], (const float*)d_in[4],
                         (const float*)d_in[6], (const float*)d_in[8]};
    const float* b[4] = {(const float*)d_in[3], (const float*)d_in[5],
                         (const float*)d_in[7], (const float*)d_in[9]};
    float* out = (float*)d_out;

    __half *Xh, *Xl, *Wh, *Qh, *Ql, *Kh, *Vh, *Ah, *Al;
    cudaGetSymbolAddress((void**)&Xh, g_Xh);
    cudaGetSymbolAddress((void**)&Xl, g_Xl);
    cudaGetSymbolAddress((void**)&Wh, g_Wh);
    cudaGetSymbolAddress((void**)&Qh, g_Qh);
    cudaGetSymbolAddress((void**)&Ql, g_Ql);
    cudaGetSymbolAddress((void**)&Kh, g_Kh);
    cudaGetSymbolAddress((void**)&Vh, g_Vh);
    cudaGetSymbolAddress((void**)&Ah, g_Ah);
    cudaGetSymbolAddress((void**)&Al, g_Al);

    cudaFuncSetAttribute(attn_mma,
                         cudaFuncAttributeMaxDynamicSharedMemorySize, ATTN_SMEM);
    cudaFuncSetAttribute(gemm_mma_f16<0>,
                         cudaFuncAttributeMaxDynamicSharedMemorySize, GEMM_SMEM);
    cudaFuncSetAttribute(gemm_mma_f16<1>,
                         cudaFuncAttributeMaxDynamicSharedMemorySize, GEMM_SMEM);
    cudaFuncSetAttribute(gemm_mma_f16<2>,
                         cudaFuncAttributeMaxDynamicSharedMemorySize, GEMM_SMEM);

    const int nX = kT * kE;
    const int nW = kE * kE;

    split_f16<<<nX / 4 / 256, 256>>>(hs, Xh, Xl, nX);
    for (int i = 0; i < 4; i++)
        cvt_f16<<<nW / 4 / 256, 256>>>(W[i], Wh + (size_t)i * nW, nW);

    dim3 ggrid(kE / 128, kT / 128);  // (8, 32)
    gemm_mma_f16<2><<<ggrid, 256, GEMM_SMEM>>>(Xh, Xl, Wh + 0 * (size_t)nW,
                                               b[0], nullptr, Qh, Ql);
    gemm_mma_f16<1><<<ggrid, 256, GEMM_SMEM>>>(Xh, Xl, Wh + 1 * (size_t)nW,
                                               b[1], nullptr, Kh, nullptr);
    gemm_mma_f16<1><<<ggrid, 256, GEMM_SMEM>>>(Xh, Xl, Wh + 2 * (size_t)nW,
                                               b[2], nullptr, Vh, nullptr);

    attn_mma<<<dim3(kT / 64, kH), 128, ATTN_SMEM>>>(Qh, Ql, Kh, Vh, cu, Ah, Al);

    gemm_mma_f16<0><<<ggrid, 256, GEMM_SMEM>>>(Ah, Al, Wh + 3 * (size_t)nW,
                                               b[3], out, nullptr, nullptr);
}

// round 7
// speedup vs baseline: 1.6325x; 1.1234x over previous
#include <cuda_runtime.h>
#include <cuda_fp16.h>
#include <math.h>
#include <cstdint>

// Problem constants
#define kT 4096
#define kE 1024
#define kH 16
#define kD 64

// ---------------------------------------------------------------------------
// Scratch (__device__ globals; allocation-free rule)
// ---------------------------------------------------------------------------
__device__ __half g_Xh[kT * kE];
__device__ __half g_Xl[kT * kE];
__device__ __half g_Wh[4][kE * kE];   // q,k,v,o weights, hi only
__device__ __half g_Qh[kT * kE];
__device__ __half g_Kh[kT * kE];
__device__ __half g_Vh[kT * kE];
__device__ __half g_Ah[kT * kE];      // attention out, hi only

// ---------------------------------------------------------------------------
// Helpers (plain PTX, compute_103-safe)
// ---------------------------------------------------------------------------
__device__ __forceinline__ uint32_t smem_u32(const void* p) {
    uint32_t a;
    asm("{ .reg .u64 t; cvta.to.shared.u64 t, %1; cvt.u32.u64 %0, t; }"
        : "=r"(a) : "l"(p));
    return a;
}

__device__ __forceinline__ void cp16(uint32_t dst, const void* src) {
    asm volatile("cp.async.cg.shared.global [%0], [%1], 16;"
                 :: "r"(dst), "l"(src) : "memory");
}
#define CP_COMMIT() asm volatile("cp.async.commit_group;" ::: "memory")
#define CP_WAIT(n)  asm volatile("cp.async.wait_group %0;" :: "n"(n) : "memory")

__device__ __forceinline__ void ldsm_x4(uint32_t& r0, uint32_t& r1,
                                        uint32_t& r2, uint32_t& r3,
                                        uint32_t addr) {
    asm volatile("ldmatrix.sync.aligned.m8n8.x4.shared.b16 {%0,%1,%2,%3}, [%4];"
                 : "=r"(r0), "=r"(r1), "=r"(r2), "=r"(r3) : "r"(addr));
}

__device__ __forceinline__ void ldsm_x4_trans(uint32_t& r0, uint32_t& r1,
                                              uint32_t& r2, uint32_t& r3,
                                              uint32_t addr) {
    asm volatile("ldmatrix.sync.aligned.m8n8.x4.trans.shared.b16 {%0,%1,%2,%3}, [%4];"
                 : "=r"(r0), "=r"(r1), "=r"(r2), "=r"(r3) : "r"(addr));
}

// NOTE: non-volatile — pure register computation; lets ptxas schedule freely.
__device__ __forceinline__ void mma_f16(float& d0, float& d1, float& d2, float& d3,
                                        uint32_t a0, uint32_t a1, uint32_t a2,
                                        uint32_t a3, uint32_t b0, uint32_t b1) {
    asm("mma.sync.aligned.m16n8k16.row.col.f32.f16.f16.f32 "
        "{%0,%1,%2,%3}, {%4,%5,%6,%7}, {%8,%9}, {%0,%1,%2,%3};"
        : "+f"(d0), "+f"(d1), "+f"(d2), "+f"(d3)
        : "r"(a0), "r"(a1), "r"(a2), "r"(a3), "r"(b0), "r"(b1));
}

__device__ __forceinline__ uint32_t pack_f16(float a, float b) {
    __half ha = __float2half_rn(a);
    __half hb = __float2half_rn(b);
    return ((uint32_t)__half_as_ushort(hb) << 16) | __half_as_ushort(ha);
}

// ---------------------------------------------------------------------------
// Elementwise converts
// ---------------------------------------------------------------------------
__global__ void split_f16(const float* __restrict__ in,
                          __half* __restrict__ hi,
                          __half* __restrict__ lo, int n) {
    int i = (blockIdx.x * blockDim.x + threadIdx.x) * 4;
    if (i >= n) return;
    float4 x = *(const float4*)(in + i);
    __half h0 = __float2half_rn(x.x);
    __half h1 = __float2half_rn(x.y);
    __half h2 = __float2half_rn(x.z);
    __half h3 = __float2half_rn(x.w);
    uint2 ph, pl;
    ph.x = ((uint32_t)__half_as_ushort(h1) << 16) | __half_as_ushort(h0);
    ph.y = ((uint32_t)__half_as_ushort(h3) << 16) | __half_as_ushort(h2);
    pl.x = pack_f16(x.x - __half2float(h0), x.y - __half2float(h1));
    pl.y = pack_f16(x.z - __half2float(h2), x.w - __half2float(h3));
    *(uint2*)(hi + i) = ph;
    *(uint2*)(lo + i) = pl;
}

// Convert 4 weight matrices in one launch: in_ptrs indexed by blockIdx.y
__global__ void cvt_w4(const float* __restrict__ w0, const float* __restrict__ w1,
                       const float* __restrict__ w2, const float* __restrict__ w3,
                       __half* __restrict__ hi, int n) {
    const float* src = (blockIdx.y == 0) ? w0 : (blockIdx.y == 1) ? w1
                       : (blockIdx.y == 2) ? w2 : w3;
    __half* dst = hi + (size_t)blockIdx.y * n;
    int i = (blockIdx.x * blockDim.x + threadIdx.x) * 4;
    if (i >= n) return;
    float4 x = *(const float4*)(src + i);
    uint2 ph;
    ph.x = pack_f16(x.x, x.y);
    ph.y = pack_f16(x.z, x.w);
    *(uint2*)(dst + i) = ph;
}

// ---------------------------------------------------------------------------
// Warp-MMA fp16 GEMM-NT + bias, cp.async double-buffered.
// Y[m,n] = sum_k X[m,k]*W[n,k] + b[n].  CTA 128x128, 8 warps, K-chunk 32.
// ACORR: D = Ah*Bh + Al*Bh (A-side compensated); else D = Ah*Bh.
// OUTMODE: 0 = fp32, 1 = fp16 hi only.
// MMA issue order: all independent hi-MMAs first, then lo pass (reuse
// distance 16 per accumulator -> hides HMMA latency).
// ---------------------------------------------------------------------------
#define KCH 32
#define ASTR 40                       // fp16 units per row
#define TILE_E (128 * ASTR)           // 5120 halfs = 10240 B per tile
#define STAGE_E (3 * TILE_E)
#define GEMM_SMEM (2 * STAGE_E * 2)   // 61440 B

template <int OUTMODE, bool ACORR>
__global__ __launch_bounds__(256, 2)
void gemm_mma_f16(const __half* __restrict__ Ahg,
                  const __half* __restrict__ Alg,
                  const __half* __restrict__ Bhg,
                  const float* __restrict__ bias,
                  float* __restrict__ Yf,
                  __half* __restrict__ Yh) {
    extern __shared__ __half dsm[];

    const int tid = threadIdx.x;
    const int wid = tid >> 5;
    const int lid = tid & 31;
    const int wm = (wid & 3) * 32;
    const int wn = (wid >> 2) * 64;
    const int row0 = blockIdx.y * 128;
    const int col0 = blockIdx.x * 128;

    const uint32_t ubase = smem_u32(dsm);

    const int r_ld[2] = {tid >> 2, (tid + 256) >> 2};
    const int c_ld[2] = {(tid & 3) * 8, ((tid + 256) & 3) * 8};

    float acc[2][8][4];
#pragma unroll
    for (int i = 0; i < 2; i++)
#pragma unroll
        for (int j = 0; j < 8; j++)
#pragma unroll
            for (int c = 0; c < 4; c++) acc[i][j][c] = 0.0f;

    const int lrow = lid & 15;
    const int lkhalf = (lid >> 4) * 8;
    const int bn = (lid >> 4) * 8 + (lid & 7);
    const int bk = ((lid >> 3) & 1) * 8;

    // prefetch stage 0
#pragma unroll
    for (int i = 0; i < 2; i++) {
        uint32_t so = ubase + (uint32_t)(r_ld[i] * ASTR + c_ld[i]) * 2;
        size_t ga = (size_t)(row0 + r_ld[i]) * kE + c_ld[i];
        size_t gb = (size_t)(col0 + r_ld[i]) * kE + c_ld[i];
        cp16(so, Ahg + ga);
        if (ACORR) cp16(so + TILE_E * 2, Alg + ga);
        cp16(so + 2 * TILE_E * 2, Bhg + gb);
    }
    CP_COMMIT();

    const int NS = kE / KCH;
    for (int s = 0; s < NS; s++) {
        if (s + 1 < NS) {
            int k0n = (s + 1) * KCH;
            uint32_t stb = ubase + ((s + 1) & 1) * (STAGE_E * 2);
#pragma unroll
            for (int i = 0; i < 2; i++) {
                uint32_t so = stb + (uint32_t)(r_ld[i] * ASTR + c_ld[i]) * 2;
                size_t ga = (size_t)(row0 + r_ld[i]) * kE + k0n + c_ld[i];
                size_t gb = (size_t)(col0 + r_ld[i]) * kE + k0n + c_ld[i];
                cp16(so, Ahg + ga);
                if (ACORR) cp16(so + TILE_E * 2, Alg + ga);
                cp16(so + 2 * TILE_E * 2, Bhg + gb);
            }
            CP_COMMIT();
            CP_WAIT(1);
        } else {
            CP_WAIT(0);
        }
        __syncthreads();

        const uint32_t uAh = ubase + (s & 1) * (STAGE_E * 2);
        const uint32_t uAl = uAh + TILE_E * 2;
        const uint32_t uBh = uAh + 2 * TILE_E * 2;

#pragma unroll
        for (int kk = 0; kk < KCH; kk += 16) {
            uint32_t ah[2][4], al[2][4], bh[4][4];
#pragma unroll
            for (int i = 0; i < 2; i++) {
                uint32_t off = (uint32_t)((wm + i * 16 + lrow) * ASTR + kk + lkhalf) * 2;
                ldsm_x4(ah[i][0], ah[i][1], ah[i][2], ah[i][3], uAh + off);
                if (ACORR)
                    ldsm_x4(al[i][0], al[i][1], al[i][2], al[i][3], uAl + off);
            }
#pragma unroll
            for (int p = 0; p < 4; p++) {
                uint32_t boff = (uint32_t)((wn + p * 16 + bn) * ASTR + kk + bk) * 2;
                ldsm_x4(bh[p][0], bh[p][1], bh[p][2], bh[p][3], uBh + boff);
            }
            // hi pass: 16 independent MMAs
#pragma unroll
            for (int p = 0; p < 4; p++)
#pragma unroll
                for (int i = 0; i < 2; i++) {
                    float* d0 = acc[i][p * 2];
                    float* d1 = acc[i][p * 2 + 1];
                    mma_f16(d0[0], d0[1], d0[2], d0[3],
                            ah[i][0], ah[i][1], ah[i][2], ah[i][3],
                            bh[p][0], bh[p][1]);
                    mma_f16(d1[0], d1[1], d1[2], d1[3],
                            ah[i][0], ah[i][1], ah[i][2], ah[i][3],
                            bh[p][2], bh[p][3]);
                }
            // lo pass
            if (ACORR) {
#pragma unroll
                for (int p = 0; p < 4; p++)
#pragma unroll
                    for (int i = 0; i < 2; i++) {
                        float* d0 = acc[i][p * 2];
                        float* d1 = acc[i][p * 2 + 1];
                        mma_f16(d0[0], d0[1], d0[2], d0[3],
                                al[i][0], al[i][1], al[i][2], al[i][3],
                                bh[p][0], bh[p][1]);
                        mma_f16(d1[0], d1[1], d1[2], d1[3],
                                al[i][0], al[i][1], al[i][2], al[i][3],
                                bh[p][2], bh[p][3]);
                    }
            }
        }
        __syncthreads();
    }

    const int erow = lid >> 2;
    const int ecol = (lid & 3) * 2;
#pragma unroll
    for (int i = 0; i < 2; i++) {
        int r = row0 + wm + i * 16 + erow;
#pragma unroll
        for (int j = 0; j < 8; j++) {
            int c = col0 + wn + j * 8 + ecol;
            float b0 = bias[c], b1 = bias[c + 1];
            float v00 = acc[i][j][0] + b0, v01 = acc[i][j][1] + b1;
            float v10 = acc[i][j][2] + b0, v11 = acc[i][j][3] + b1;
            if (OUTMODE == 0) {
                *(float2*)(Yf + (size_t)r * kE + c) = make_float2(v00, v01);
                *(float2*)(Yf + (size_t)(r + 8) * kE + c) = make_float2(v10, v11);
            } else {
                *(uint32_t*)(Yh + (size_t)r * kE + c) = pack_f16(v00, v01);
                *(uint32_t*)(Yh + (size_t)(r + 8) * kE + c) = pack_f16(v10, v11);
            }
        }
    }
}

// ---------------------------------------------------------------------------
// Varlen flash attention, fp16 mma.
// S = Qh*Kh (uncorrected; score error ~1e-4);  O += Ph*Vh + Pl*Vh.
// Grid (kT/64, kH), 128 threads (4 warps), warp w -> q rows w*16..+16.
// ---------------------------------------------------------------------------
#define QSTR 72
// halfs: Qh 0, Kh 4608, Vh 9216, end 13824
#define ATTN_SMEM (13824 * 2 + 2 * 64 * 4)

__global__ __launch_bounds__(128)
void attn_mma(const __half* __restrict__ Qhg,
              const __half* __restrict__ Khg,
              const __half* __restrict__ Vhg,
              const int* __restrict__ cu,
              __half* __restrict__ Oh) {
    extern __shared__ __half sb[];
    __half* sQh = sb;
    __half* sKh = sb + 4608;
    __half* sVh = sb + 9216;
    int* s_lo = (int*)(sb + 13824);
    int* s_hi = s_lo + 64;

    const int tid = threadIdx.x;
    const int wid = tid >> 5;
    const int lid = tid & 31;
    const int q0 = blockIdx.x * 64;
    const int hcol = blockIdx.y * kD;
    const int wm = wid * 16;

    const uint32_t uQh = smem_u32(sQh);
    const uint32_t uKh = smem_u32(sKh);
    const uint32_t uVh = smem_u32(sVh);

    if (tid < 64) {
        int r = q0 + tid;
        int lo = 0, hi = kT;
#pragma unroll
        for (int s = 0; s < 8; s++) {
            int a = cu[s], b = cu[s + 1];
            if (r >= a && r < b) { lo = a; hi = b; }
        }
        s_lo[tid] = lo;
        s_hi[tid] = hi;
    }

    // Load Q tile (hi only): 64 rows x 64 halfs
#pragma unroll
    for (int i = 0; i < 4; i++) {
        int f = tid + i * 128;
        int r = f >> 3;
        int c8 = (f & 7) * 8;
        size_t g = (size_t)(q0 + r) * kE + hcol + c8;
        *(uint4*)(sQh + r * QSTR + c8) = *(const uint4*)(Qhg + g);
    }
    __syncthreads();

    const int rrow = lid >> 2;
    int row_lo[2], row_hi[2];
    row_lo[0] = s_lo[wm + rrow];      row_hi[0] = s_hi[wm + rrow];
    row_lo[1] = s_lo[wm + rrow + 8];  row_hi[1] = s_hi[wm + rrow + 8];
    const int span_lo = s_lo[0];
    const int span_hi = s_hi[63];

    const int lrow = lid & 15;
    const int lkhalf = (lid >> 4) * 8;
    const int bn = (lid >> 4) * 8 + (lid & 7);
    const int bk = ((lid >> 3) & 1) * 8;
    const int vt = lid >> 3;
    const int vr = lid & 7;

    float m[2], l[2], o[8][4];
    m[0] = m[1] = -1e30f;
    l[0] = l[1] = 0.0f;
#pragma unroll
    for (int t = 0; t < 8; t++)
#pragma unroll
        for (int c = 0; c < 4; c++) o[t][c] = 0.0f;

    for (int kb = span_lo; kb < span_hi; kb += 64) {
        __syncthreads();
#pragma unroll
        for (int i = 0; i < 4; i++) {
            int f = tid + i * 128;
            int r = f >> 3;
            int c8 = (f & 7) * 8;
            int kg = kb + r;
            uint4 z = make_uint4(0, 0, 0, 0);
            uint4 vkh = z, vvh = z;
            if (kg < span_hi) {
                size_t g = (size_t)kg * kE + hcol + c8;
                vkh = *(const uint4*)(Khg + g);
                vvh = *(const uint4*)(Vhg + g);
            }
            int so = r * QSTR + c8;
            *(uint4*)(sKh + so) = vkh;
            *(uint4*)(sVh + so) = vvh;
        }
        __syncthreads();

        // ---- S = Q K^T (hi only) ----
        float s[8][4];
#pragma unroll
        for (int t = 0; t < 8; t++)
#pragma unroll
            for (int c = 0; c < 4; c++) s[t][c] = 0.0f;

#pragma unroll
        for (int kc = 0; kc < 4; kc++) {
            uint32_t qh[4];
            uint32_t aoff = (uint32_t)((wm + lrow) * QSTR + kc * 16 + lkhalf) * 2;
            ldsm_x4(qh[0], qh[1], qh[2], qh[3], uQh + aoff);
            uint32_t kh[4][4];
#pragma unroll
            for (int p = 0; p < 4; p++) {
                uint32_t boff = (uint32_t)((p * 16 + bn) * QSTR + kc * 16 + bk) * 2;
                ldsm_x4(kh[p][0], kh[p][1], kh[p][2], kh[p][3], uKh + boff);
            }
#pragma unroll
            for (int p = 0; p < 4; p++) {
                float* d0 = s[p * 2];
                float* d1 = s[p * 2 + 1];
                mma_f16(d0[0], d0[1], d0[2], d0[3],
                        qh[0], qh[1], qh[2], qh[3], kh[p][0], kh[p][1]);
                mma_f16(d1[0], d1[1], d1[2], d1[3],
                        qh[0], qh[1], qh[2], qh[3], kh[p][2], kh[p][3]);
            }
        }

        // ---- scale + mask + online softmax ----
        const int colb = (lid & 3) * 2;
#pragma unroll
        for (int i = 0; i < 2; i++) {
            float rm = -1e30f;
#pragma unroll
            for (int t = 0; t < 8; t++) {
                int kg0 = kb + t * 8 + colb;
                float v0 = s[t][2 * i] * 0.125f;
                float v1 = s[t][2 * i + 1] * 0.125f;
                if (kg0 < row_lo[i] || kg0 >= row_hi[i]) v0 = -1e30f;
                if (kg0 + 1 < row_lo[i] || kg0 + 1 >= row_hi[i]) v1 = -1e30f;
                s[t][2 * i] = v0;
                s[t][2 * i + 1] = v1;
                rm = fmaxf(rm, fmaxf(v0, v1));
            }
            rm = fmaxf(rm, __shfl_xor_sync(0xffffffffu, rm, 1));
            rm = fmaxf(rm, __shfl_xor_sync(0xffffffffu, rm, 2));

            float mn = fmaxf(m[i], rm);
            float c = __expf(m[i] - mn);
            float rs = 0.0f;
#pragma unroll
            for (int t = 0; t < 8; t++) {
                float v0 = s[t][2 * i];
                float v1 = s[t][2 * i + 1];
                float p0 = (v0 <= -1e29f) ? 0.0f : __expf(v0 - mn);
                float p1 = (v1 <= -1e29f) ? 0.0f : __expf(v1 - mn);
                s[t][2 * i] = p0;
                s[t][2 * i + 1] = p1;
                rs += p0 + p1;
            }
            rs += __shfl_xor_sync(0xffffffffu, rs, 1);
            rs += __shfl_xor_sync(0xffffffffu, rs, 2);

            l[i] = l[i] * c + rs;
            m[i] = mn;
#pragma unroll
            for (int t = 0; t < 8; t++) {
                o[t][2 * i] *= c;
                o[t][2 * i + 1] *= c;
            }
        }

        // ---- O += P V (P split hi/lo; hi pass then lo pass per kc) ----
#pragma unroll
        for (int kc = 0; kc < 4; kc++) {
            int t0 = 2 * kc, t1 = 2 * kc + 1;
            uint32_t ph[4], pl[4];
            {
                __half h0, h1;
                float f0, f1;
                f0 = s[t0][0]; f1 = s[t0][1];
                h0 = __float2half_rn(f0); h1 = __float2half_rn(f1);
                ph[0] = ((uint32_t)__half_as_ushort(h1) << 16) | __half_as_ushort(h0);
                pl[0] = pack_f16(f0 - __half2float(h0), f1 - __half2float(h1));
                f0 = s[t0][2]; f1 = s[t0][3];
                h0 = __float2half_rn(f0); h1 = __float2half_rn(f1);
                ph[1] = ((uint32_t)__half_as_ushort(h1) << 16) | __half_as_ushort(h0);
                pl[1] = pack_f16(f0 - __half2float(h0), f1 - __half2float(h1));
                f0 = s[t1][0]; f1 = s[t1][1];
                h0 = __float2half_rn(f0); h1 = __float2half_rn(f1);
                ph[2] = ((uint32_t)__half_as_ushort(h1) << 16) | __half_as_ushort(h0);
                pl[2] = pack_f16(f0 - __half2float(h0), f1 - __half2float(h1));
                f0 = s[t1][2]; f1 = s[t1][3];
                h0 = __float2half_rn(f0); h1 = __float2half_rn(f1);
                ph[3] = ((uint32_t)__half_as_ushort(h1) << 16) | __half_as_ushort(h0);
                pl[3] = pack_f16(f0 - __half2float(h0), f1 - __half2float(h1));
            }
            uint32_t vh[4][4];
#pragma unroll
            for (int dp = 0; dp < 4; dp++) {
                uint32_t voff = (uint32_t)((kc * 16 + (vt & 1) * 8 + vr) * QSTR +
                                           dp * 16 + (vt >> 1) * 8) * 2;
                ldsm_x4_trans(vh[dp][0], vh[dp][1], vh[dp][2], vh[dp][3], uVh + voff);
            }
#pragma unroll
            for (int dp = 0; dp < 4; dp++) {
                float* d0 = o[dp * 2];
                float* d1 = o[dp * 2 + 1];
                mma_f16(d0[0], d0[1], d0[2], d0[3],
                        ph[0], ph[1], ph[2], ph[3], vh[dp][0], vh[dp][1]);
                mma_f16(d1[0], d1[1], d1[2], d1[3],
                        ph[0], ph[1], ph[2], ph[3], vh[dp][2], vh[dp][3]);
            }
#pragma unroll
            for (int dp = 0; dp < 4; dp++) {
                float* d0 = o[dp * 2];
                float* d1 = o[dp * 2 + 1];
                mma_f16(d0[0], d0[1], d0[2], d0[3],
                        pl[0], pl[1], pl[2], pl[3], vh[dp][0], vh[dp][1]);
                mma_f16(d1[0], d1[1], d1[2], d1[3],
                        pl[0], pl[1], pl[2], pl[3], vh[dp][2], vh[dp][3]);
            }
        }
    }

    float inv0 = 1.0f / l[0];
    float inv1 = 1.0f / l[1];
    const int colb = (lid & 3) * 2;
#pragma unroll
    for (int t = 0; t < 8; t++) {
        int col = hcol + t * 8 + colb;
        int r0 = q0 + wm + rrow;
        *(uint32_t*)(Oh + (size_t)r0 * kE + col) =
            pack_f16(o[t][0] * inv0, o[t][1] * inv0);
        *(uint32_t*)(Oh + (size_t)(r0 + 8) * kE + col) =
            pack_f16(o[t][2] * inv1, o[t][3] * inv1);
    }
}

// ---------------------------------------------------------------------------
extern "C" void kernel_launch(void* const* d_in, const int* in_sizes, int n_in,
                              void* d_out, int out_size) {
    const float* hs = (const float*)d_in[0];
    const int* cu   = (const int*)d_in[1];
    const float* W[4] = {(const float*)d_in[2], (const float*)d_in[4],
                         (const float*)d_in[6], (const float*)d_in[8]};
    const float* b[4] = {(const float*)d_in[3], (const float*)d_in[5],
                         (const float*)d_in[7], (const float*)d_in[9]};
    float* out = (float*)d_out;

    __half *Xh, *Xl, *Wh, *Qh, *Kh, *Vh, *Ah;
    cudaGetSymbolAddress((void**)&Xh, g_Xh);
    cudaGetSymbolAddress((void**)&Xl, g_Xl);
    cudaGetSymbolAddress((void**)&Wh, g_Wh);
    cudaGetSymbolAddress((void**)&Qh, g_Qh);
    cudaGetSymbolAddress((void**)&Kh, g_Kh);
    cudaGetSymbolAddress((void**)&Vh, g_Vh);
    cudaGetSymbolAddress((void**)&Ah, g_Ah);

    cudaFuncSetAttribute(attn_mma,
                         cudaFuncAttributeMaxDynamicSharedMemorySize, ATTN_SMEM);
    cudaFuncSetAttribute(gemm_mma_f16<1, true>,
                         cudaFuncAttributeMaxDynamicSharedMemorySize, GEMM_SMEM);
    cudaFuncSetAttribute(gemm_mma_f16<0, false>,
                         cudaFuncAttributeMaxDynamicSharedMemorySize, GEMM_SMEM);

    const int nX = kT * kE;
    const int nW = kE * kE;

    split_f16<<<nX / 4 / 256, 256>>>(hs, Xh, Xl, nX);
    cvt_w4<<<dim3(nW / 4 / 256, 4), 256>>>(W[0], W[1], W[2], W[3], Wh, nW);

    dim3 ggrid(kE / 128, kT / 128);  // (8, 32)
    gemm_mma_f16<1, true><<<ggrid, 256, GEMM_SMEM>>>(
        Xh, Xl, Wh + 0 * (size_t)nW, b[0], nullptr, Qh);
    gemm_mma_f16<1, true><<<ggrid, 256, GEMM_SMEM>>>(
        Xh, Xl, Wh + 1 * (size_t)nW, b[1], nullptr, Kh);
    gemm_mma_f16<1, true><<<ggrid, 256, GEMM_SMEM>>>(
        Xh, Xl, Wh + 2 * (size_t)nW, b[2], nullptr, Vh);

    attn_mma<<<dim3(kT / 64, kH), 128, ATTN_SMEM>>>(Qh, Kh, Vh, cu, Ah);

    gemm_mma_f16<0, false><<<ggrid, 256, GEMM_SMEM>>>(
        Ah, nullptr, Wh + 3 * (size_t)nW, b[3], out, nullptr);
}

// round 8
// speedup vs baseline: 2.3365x; 1.4313x over previous
#include <cuda_runtime.h>
#include <cuda_fp16.h>
#include <math.h>
#include <cstdint>

// Problem constants
#define kT 4096
#define kE 1024
#define kH 16
#define kD 64

// ---------------------------------------------------------------------------
// Scratch (__device__ globals; allocation-free rule)
// ---------------------------------------------------------------------------
__device__ __half g_Xh[kT * kE];
__device__ __half g_Wh[4][kE * kE];   // q,k,v,o weights (fp16 hi)
__device__ __half g_Qh[kT * kE];
__device__ __half g_Kh[kT * kE];
__device__ __half g_Vh[kT * kE];
__device__ __half g_Ah[kT * kE];      // attention out

// ---------------------------------------------------------------------------
// Helpers (plain PTX, compute_103-safe)
// ---------------------------------------------------------------------------
__device__ __forceinline__ uint32_t smem_u32(const void* p) {
    uint32_t a;
    asm("{ .reg .u64 t; cvta.to.shared.u64 t, %1; cvt.u32.u64 %0, t; }"
        : "=r"(a) : "l"(p));
    return a;
}

__device__ __forceinline__ void cp16(uint32_t dst, const void* src) {
    asm volatile("cp.async.cg.shared.global [%0], [%1], 16;"
                 :: "r"(dst), "l"(src) : "memory");
}
#define CP_COMMIT() asm volatile("cp.async.commit_group;" ::: "memory")
#define CP_WAIT(n)  asm volatile("cp.async.wait_group %0;" :: "n"(n) : "memory")

__device__ __forceinline__ void ldsm_x4(uint32_t& r0, uint32_t& r1,
                                        uint32_t& r2, uint32_t& r3,
                                        uint32_t addr) {
    asm volatile("ldmatrix.sync.aligned.m8n8.x4.shared.b16 {%0,%1,%2,%3}, [%4];"
                 : "=r"(r0), "=r"(r1), "=r"(r2), "=r"(r3) : "r"(addr));
}

__device__ __forceinline__ void ldsm_x4_trans(uint32_t& r0, uint32_t& r1,
                                              uint32_t& r2, uint32_t& r3,
                                              uint32_t addr) {
    asm volatile("ldmatrix.sync.aligned.m8n8.x4.trans.shared.b16 {%0,%1,%2,%3}, [%4];"
                 : "=r"(r0), "=r"(r1), "=r"(r2), "=r"(r3) : "r"(addr));
}

__device__ __forceinline__ void mma_f16(float& d0, float& d1, float& d2, float& d3,
                                        uint32_t a0, uint32_t a1, uint32_t a2,
                                        uint32_t a3, uint32_t b0, uint32_t b1) {
    asm("mma.sync.aligned.m16n8k16.row.col.f32.f16.f16.f32 "
        "{%0,%1,%2,%3}, {%4,%5,%6,%7}, {%8,%9}, {%0,%1,%2,%3};"
        : "+f"(d0), "+f"(d1), "+f"(d2), "+f"(d3)
        : "r"(a0), "r"(a1), "r"(a2), "r"(a3), "r"(b0), "r"(b1));
}

__device__ __forceinline__ uint32_t pack_f16(float a, float b) {
    __half ha = __float2half_rn(a);
    __half hb = __float2half_rn(b);
    return ((uint32_t)__half_as_ushort(hb) << 16) | __half_as_ushort(ha);
}

// ---------------------------------------------------------------------------
// Elementwise converts
// ---------------------------------------------------------------------------
__global__ void cvt_f16(const float* __restrict__ in, __half* __restrict__ hi,
                        int n) {
    int i = (blockIdx.x * blockDim.x + threadIdx.x) * 4;
    if (i >= n) return;
    float4 x = *(const float4*)(in + i);
    uint2 ph;
    ph.x = pack_f16(x.x, x.y);
    ph.y = pack_f16(x.z, x.w);
    *(uint2*)(hi + i) = ph;
}

__global__ void cvt_w4(const float* __restrict__ w0, const float* __restrict__ w1,
                       const float* __restrict__ w2, const float* __restrict__ w3,
                       __half* __restrict__ hi, int n) {
    const float* src = (blockIdx.y == 0) ? w0 : (blockIdx.y == 1) ? w1
                       : (blockIdx.y == 2) ? w2 : w3;
    __half* dst = hi + (size_t)blockIdx.y * n;
    int i = (blockIdx.x * blockDim.x + threadIdx.x) * 4;
    if (i >= n) return;
    float4 x = *(const float4*)(src + i);
    uint2 ph;
    ph.x = pack_f16(x.x, x.y);
    ph.y = pack_f16(x.z, x.w);
    *(uint2*)(dst + i) = ph;
}

// ---------------------------------------------------------------------------
// Warp-MMA fp16 single-term GEMM-NT + bias, cp.async double-buffered.
// Y[m,n] = sum_k A[m,k]*B[n,k] + b[n].  CTA 128x128, 8 warps, K-chunk 64.
// OUTMODE: 0 = fp32 out, 1 = fp16 out.
// ---------------------------------------------------------------------------
#define KCH 64
#define ASTR 72                        // fp16 units per row (64 + 8 pad)
#define TILE_B (128 * ASTR * 2)        // 18432 bytes per tile
#define GEMM_SMEM (2 * 2 * TILE_B)     // 2 stages x (A,B) = 73728 B

template <int OUTMODE>
__device__ __forceinline__ void gemm_body(const __half* __restrict__ Ahg,
                                          const __half* __restrict__ Bhg,
                                          const float* __restrict__ bias,
                                          float* __restrict__ Yf,
                                          __half* __restrict__ Yh) {
    extern __shared__ __half dsm[];

    const int tid = threadIdx.x;
    const int wid = tid >> 5;
    const int lid = tid & 31;
    const int wm = (wid & 3) * 32;
    const int wn = (wid >> 2) * 64;
    const int row0 = blockIdx.y * 128;
    const int col0 = blockIdx.x * 128;

    const uint32_t ubase = smem_u32(dsm);

    float acc[2][8][4];
#pragma unroll
    for (int i = 0; i < 2; i++)
#pragma unroll
        for (int j = 0; j < 8; j++)
#pragma unroll
            for (int c = 0; c < 4; c++) acc[i][j][c] = 0.0f;

    const int lrow = lid & 15;
    const int lkhalf = (lid >> 4) * 8;
    const int bn = (lid >> 4) * 8 + (lid & 7);
    const int bk = ((lid >> 3) & 1) * 8;

    // Per-stage load: A tile 128x64 halfs = 1024 16B-chunks, same for B.
    // Thread slots: i=0..3 -> A chunk tid+i*256, i=0..3 -> B chunk tid+i*256.
#define GEMM_LOAD(stb, k0)                                                    \
    do {                                                                      \
        _Pragma("unroll")                                                     \
        for (int i = 0; i < 4; i++) {                                         \
            int g = tid + i * 256;                                            \
            int r = g >> 3, c8 = (g & 7) * 8;                                 \
            uint32_t so = (stb) + (uint32_t)(r * ASTR + c8) * 2;              \
            cp16(so, Ahg + (size_t)(row0 + r) * kE + (k0) + c8);              \
            cp16(so + TILE_B, Bhg + (size_t)(col0 + r) * kE + (k0) + c8);     \
        }                                                                     \
    } while (0)

    GEMM_LOAD(ubase, 0);
    CP_COMMIT();

    const int NS = kE / KCH;  // 16
    for (int s = 0; s < NS; s++) {
        if (s + 1 < NS) {
            uint32_t stb = ubase + ((s + 1) & 1) * (2 * TILE_B);
            GEMM_LOAD(stb, (s + 1) * KCH);
            CP_COMMIT();
            CP_WAIT(1);
        } else {
            CP_WAIT(0);
        }
        __syncthreads();

        const uint32_t uA = ubase + (s & 1) * (2 * TILE_B);
        const uint32_t uB = uA + TILE_B;

#pragma unroll
        for (int kk = 0; kk < KCH; kk += 16) {
            uint32_t ah[2][4], bh[4][4];
#pragma unroll
            for (int i = 0; i < 2; i++) {
                uint32_t off = (uint32_t)((wm + i * 16 + lrow) * ASTR + kk + lkhalf) * 2;
                ldsm_x4(ah[i][0], ah[i][1], ah[i][2], ah[i][3], uA + off);
            }
#pragma unroll
            for (int p = 0; p < 4; p++) {
                uint32_t boff = (uint32_t)((wn + p * 16 + bn) * ASTR + kk + bk) * 2;
                ldsm_x4(bh[p][0], bh[p][1], bh[p][2], bh[p][3], uB + boff);
            }
#pragma unroll
            for (int p = 0; p < 4; p++)
#pragma unroll
                for (int i = 0; i < 2; i++) {
                    float* d0 = acc[i][p * 2];
                    float* d1 = acc[i][p * 2 + 1];
                    mma_f16(d0[0], d0[1], d0[2], d0[3],
                            ah[i][0], ah[i][1], ah[i][2], ah[i][3],
                            bh[p][0], bh[p][1]);
                    mma_f16(d1[0], d1[1], d1[2], d1[3],
                            ah[i][0], ah[i][1], ah[i][2], ah[i][3],
                            bh[p][2], bh[p][3]);
                }
        }
        __syncthreads();
    }
#undef GEMM_LOAD

    const int erow = lid >> 2;
    const int ecol = (lid & 3) * 2;
#pragma unroll
    for (int i = 0; i < 2; i++) {
        int r = row0 + wm + i * 16 + erow;
#pragma unroll
        for (int j = 0; j < 8; j++) {
            int c = col0 + wn + j * 8 + ecol;
            float b0 = bias[c], b1 = bias[c + 1];
            float v00 = acc[i][j][0] + b0, v01 = acc[i][j][1] + b1;
            float v10 = acc[i][j][2] + b0, v11 = acc[i][j][3] + b1;
            if (OUTMODE == 0) {
                *(float2*)(Yf + (size_t)r * kE + c) = make_float2(v00, v01);
                *(float2*)(Yf + (size_t)(r + 8) * kE + c) = make_float2(v10, v11);
            } else {
                *(uint32_t*)(Yh + (size_t)r * kE + c) = pack_f16(v00, v01);
                *(uint32_t*)(Yh + (size_t)(r + 8) * kE + c) = pack_f16(v10, v11);
            }
        }
    }
}

// Fused Q/K/V projection: blockIdx.z selects weight/bias/output.
__global__ __launch_bounds__(256, 2)
void gemm_qkv(const __half* __restrict__ Xh, const __half* __restrict__ Whall,
              const float* __restrict__ bq, const float* __restrict__ bk,
              const float* __restrict__ bv,
              __half* __restrict__ Q, __half* __restrict__ K,
              __half* __restrict__ V) {
    const int z = blockIdx.z;
    const __half* B = Whall + (size_t)z * kE * kE;
    const float* bias = (z == 0) ? bq : (z == 1) ? bk : bv;
    __half* Y = (z == 0) ? Q : (z == 1) ? K : V;
    gemm_body<1>(Xh, B, bias, nullptr, Y);
}

__global__ __launch_bounds__(256, 2)
void gemm_o(const __half* __restrict__ Ah, const __half* __restrict__ Wo,
            const float* __restrict__ bias, float* __restrict__ Y) {
    gemm_body<0>(Ah, Wo, bias, Y, nullptr);
}

// ---------------------------------------------------------------------------
// Varlen flash attention (unchanged from R7; known correct).
// S = Qh*Kh;  O += Ph*Vh + Pl*Vh.
// ---------------------------------------------------------------------------
#define QSTR 72
#define ATTN_SMEM (13824 * 2 + 2 * 64 * 4)

__global__ __launch_bounds__(128)
void attn_mma(const __half* __restrict__ Qhg,
              const __half* __restrict__ Khg,
              const __half* __restrict__ Vhg,
              const int* __restrict__ cu,
              __half* __restrict__ Oh) {
    extern __shared__ __half sb[];
    __half* sQh = sb;
    __half* sKh = sb + 4608;
    __half* sVh = sb + 9216;
    int* s_lo = (int*)(sb + 13824);
    int* s_hi = s_lo + 64;

    const int tid = threadIdx.x;
    const int wid = tid >> 5;
    const int lid = tid & 31;
    const int q0 = blockIdx.x * 64;
    const int hcol = blockIdx.y * kD;
    const int wm = wid * 16;

    const uint32_t uQh = smem_u32(sQh);
    const uint32_t uKh = smem_u32(sKh);
    const uint32_t uVh = smem_u32(sVh);

    if (tid < 64) {
        int r = q0 + tid;
        int lo = 0, hi = kT;
#pragma unroll
        for (int s = 0; s < 8; s++) {
            int a = cu[s], b = cu[s + 1];
            if (r >= a && r < b) { lo = a; hi = b; }
        }
        s_lo[tid] = lo;
        s_hi[tid] = hi;
    }

#pragma unroll
    for (int i = 0; i < 4; i++) {
        int f = tid + i * 128;
        int r = f >> 3;
        int c8 = (f & 7) * 8;
        size_t g = (size_t)(q0 + r) * kE + hcol + c8;
        *(uint4*)(sQh + r * QSTR + c8) = *(const uint4*)(Qhg + g);
    }
    __syncthreads();

    const int rrow = lid >> 2;
    int row_lo[2], row_hi[2];
    row_lo[0] = s_lo[wm + rrow];      row_hi[0] = s_hi[wm + rrow];
    row_lo[1] = s_lo[wm + rrow + 8];  row_hi[1] = s_hi[wm + rrow + 8];
    const int span_lo = s_lo[0];
    const int span_hi = s_hi[63];

    const int lrow = lid & 15;
    const int lkhalf = (lid >> 4) * 8;
    const int bn = (lid >> 4) * 8 + (lid & 7);
    const int bk = ((lid >> 3) & 1) * 8;
    const int vt = lid >> 3;
    const int vr = lid & 7;

    float m[2], l[2], o[8][4];
    m[0] = m[1] = -1e30f;
    l[0] = l[1] = 0.0f;
#pragma unroll
    for (int t = 0; t < 8; t++)
#pragma unroll
        for (int c = 0; c < 4; c++) o[t][c] = 0.0f;

    for (int kb = span_lo; kb < span_hi; kb += 64) {
        __syncthreads();
#pragma unroll
        for (int i = 0; i < 4; i++) {
            int f = tid + i * 128;
            int r = f >> 3;
            int c8 = (f & 7) * 8;
            int kg = kb + r;
            uint4 z = make_uint4(0, 0, 0, 0);
            uint4 vkh = z, vvh = z;
            if (kg < span_hi) {
                size_t g = (size_t)kg * kE + hcol + c8;
                vkh = *(const uint4*)(Khg + g);
                vvh = *(const uint4*)(Vhg + g);
            }
            int so = r * QSTR + c8;
            *(uint4*)(sKh + so) = vkh;
            *(uint4*)(sVh + so) = vvh;
        }
        __syncthreads();

        float s[8][4];
#pragma unroll
        for (int t = 0; t < 8; t++)
#pragma unroll
            for (int c = 0; c < 4; c++) s[t][c] = 0.0f;

#pragma unroll
        for (int kc = 0; kc < 4; kc++) {
            uint32_t qh[4];
            uint32_t aoff = (uint32_t)((wm + lrow) * QSTR + kc * 16 + lkhalf) * 2;
            ldsm_x4(qh[0], qh[1], qh[2], qh[3], uQh + aoff);
            uint32_t kh[4][4];
#pragma unroll
            for (int p = 0; p < 4; p++) {
                uint32_t boff = (uint32_t)((p * 16 + bn) * QSTR + kc * 16 + bk) * 2;
                ldsm_x4(kh[p][0], kh[p][1], kh[p][2], kh[p][3], uKh + boff);
            }
#pragma unroll
            for (int p = 0; p < 4; p++) {
                float* d0 = s[p * 2];
                float* d1 = s[p * 2 + 1];
                mma_f16(d0[0], d0[1], d0[2], d0[3],
                        qh[0], qh[1], qh[2], qh[3], kh[p][0], kh[p][1]);
                mma_f16(d1[0], d1[1], d1[2], d1[3],
                        qh[0], qh[1], qh[2], qh[3], kh[p][2], kh[p][3]);
            }
        }

        const int colb = (lid & 3) * 2;
#pragma unroll
        for (int i = 0; i < 2; i++) {
            float rm = -1e30f;
#pragma unroll
            for (int t = 0; t < 8; t++) {
                int kg0 = kb + t * 8 + colb;
                float v0 = s[t][2 * i] * 0.125f;
                float v1 = s[t][2 * i + 1] * 0.125f;
                if (kg0 < row_lo[i] || kg0 >= row_hi[i]) v0 = -1e30f;
                if (kg0 + 1 < row_lo[i] || kg0 + 1 >= row_hi[i]) v1 = -1e30f;
                s[t][2 * i] = v0;
                s[t][2 * i + 1] = v1;
                rm = fmaxf(rm, fmaxf(v0, v1));
            }
            rm = fmaxf(rm, __shfl_xor_sync(0xffffffffu, rm, 1));
            rm = fmaxf(rm, __shfl_xor_sync(0xffffffffu, rm, 2));

            float mn = fmaxf(m[i], rm);
            float c = __expf(m[i] - mn);
            float rs = 0.0f;
#pragma unroll
            for (int t = 0; t < 8; t++) {
                float v0 = s[t][2 * i];
                float v1 = s[t][2 * i + 1];
                float p0 = (v0 <= -1e29f) ? 0.0f : __expf(v0 - mn);
                float p1 = (v1 <= -1e29f) ? 0.0f : __expf(v1 - mn);
                s[t][2 * i] = p0;
                s[t][2 * i + 1] = p1;
                rs += p0 + p1;
            }
            rs += __shfl_xor_sync(0xffffffffu, rs, 1);
            rs += __shfl_xor_sync(0xffffffffu, rs, 2);

            l[i] = l[i] * c + rs;
            m[i] = mn;
#pragma unroll
            for (int t = 0; t < 8; t++) {
                o[t][2 * i] *= c;
                o[t][2 * i + 1] *= c;
            }
        }

#pragma unroll
        for (int kc = 0; kc < 4; kc++) {
            int t0 = 2 * kc, t1 = 2 * kc + 1;
            uint32_t ph[4], pl[4];
            {
                __half h0, h1;
                float f0, f1;
                f0 = s[t0][0]; f1 = s[t0][1];
                h0 = __float2half_rn(f0); h1 = __float2half_rn(f1);
                ph[0] = ((uint32_t)__half_as_ushort(h1) << 16) | __half_as_ushort(h0);
                pl[0] = pack_f16(f0 - __half2float(h0), f1 - __half2float(h1));
                f0 = s[t0][2]; f1 = s[t0][3];
                h0 = __float2half_rn(f0); h1 = __float2half_rn(f1);
                ph[1] = ((uint32_t)__half_as_ushort(h1) << 16) | __half_as_ushort(h0);
                pl[1] = pack_f16(f0 - __half2float(h0), f1 - __half2float(h1));
                f0 = s[t1][0]; f1 = s[t1][1];
                h0 = __float2half_rn(f0); h1 = __float2half_rn(f1);
                ph[2] = ((uint32_t)__half_as_ushort(h1) << 16) | __half_as_ushort(h0);
                pl[2] = pack_f16(f0 - __half2float(h0), f1 - __half2float(h1));
                f0 = s[t1][2]; f1 = s[t1][3];
                h0 = __float2half_rn(f0); h1 = __float2half_rn(f1);
                ph[3] = ((uint32_t)__half_as_ushort(h1) << 16) | __half_as_ushort(h0);
                pl[3] = pack_f16(f0 - __half2float(h0), f1 - __half2float(h1));
            }
            uint32_t vh[4][4];
#pragma unroll
            for (int dp = 0; dp < 4; dp++) {
                uint32_t voff = (uint32_t)((kc * 16 + (vt & 1) * 8 + vr) * QSTR +
                                           dp * 16 + (vt >> 1) * 8) * 2;
                ldsm_x4_trans(vh[dp][0], vh[dp][1], vh[dp][2], vh[dp][3], uVh + voff);
            }
#pragma unroll
            for (int dp = 0; dp < 4; dp++) {
                float* d0 = o[dp * 2];
                float* d1 = o[dp * 2 + 1];
                mma_f16(d0[0], d0[1], d0[2], d0[3],
                        ph[0], ph[1], ph[2], ph[3], vh[dp][0], vh[dp][1]);
                mma_f16(d1[0], d1[1], d1[2], d1[3],
                        ph[0], ph[1], ph[2], ph[3], vh[dp][2], vh[dp][3]);
            }
#pragma unroll
            for (int dp = 0; dp < 4; dp++) {
                float* d0 = o[dp * 2];
                float* d1 = o[dp * 2 + 1];
                mma_f16(d0[0], d0[1], d0[2], d0[3],
                        pl[0], pl[1], pl[2], pl[3], vh[dp][0], vh[dp][1]);
                mma_f16(d1[0], d1[1], d1[2], d1[3],
                        pl[0], pl[1], pl[2], pl[3], vh[dp][2], vh[dp][3]);
            }
        }
    }

    float inv0 = 1.0f / l[0];
    float inv1 = 1.0f / l[1];
    const int colb = (lid & 3) * 2;
#pragma unroll
    for (int t = 0; t < 8; t++) {
        int col = hcol + t * 8 + colb;
        int r0 = q0 + wm + rrow;
        *(uint32_t*)(Oh + (size_t)r0 * kE + col) =
            pack_f16(o[t][0] * inv0, o[t][1] * inv0);
        *(uint32_t*)(Oh + (size_t)(r0 + 8) * kE + col) =
            pack_f16(o[t][2] * inv1, o[t][3] * inv1);
    }
}

// ---------------------------------------------------------------------------
extern "C" void kernel_launch(void* const* d_in, const int* in_sizes, int n_in,
                              void* d_out, int out_size) {
    const float* hs = (const float*)d_in[0];
    const int* cu   = (const int*)d_in[1];
    const float* W[4] = {(const float*)d_in[2], (const float*)d_in[4],
                         (const float*)d_in[6], (const float*)d_in[8]};
    const float* b[4] = {(const float*)d_in[3], (const float*)d_in[5],
                         (const float*)d_in[7], (const float*)d_in[9]};
    float* out = (float*)d_out;

    __half *Xh, *Wh, *Qh, *Kh, *Vh, *Ah;
    cudaGetSymbolAddress((void**)&Xh, g_Xh);
    cudaGetSymbolAddress((void**)&Wh, g_Wh);
    cudaGetSymbolAddress((void**)&Qh, g_Qh);
    cudaGetSymbolAddress((void**)&Kh, g_Kh);
    cudaGetSymbolAddress((void**)&Vh, g_Vh);
    cudaGetSymbolAddress((void**)&Ah, g_Ah);

    cudaFuncSetAttribute(attn_mma,
                         cudaFuncAttributeMaxDynamicSharedMemorySize, ATTN_SMEM);
    cudaFuncSetAttribute(gemm_qkv,
                         cudaFuncAttributeMaxDynamicSharedMemorySize, GEMM_SMEM);
    cudaFuncSetAttribute(gemm_o,
                         cudaFuncAttributeMaxDynamicSharedMemorySize, GEMM_SMEM);

    const int nX = kT * kE;
    const int nW = kE * kE;

    cvt_f16<<<nX / 4 / 256, 256>>>(hs, Xh, nX);
    cvt_w4<<<dim3(nW / 4 / 256, 4), 256>>>(W[0], W[1], W[2], W[3], Wh, nW);

    gemm_qkv<<<dim3(kE / 128, kT / 128, 3), 256, GEMM_SMEM>>>(
        Xh, Wh, b[0], b[1], b[2], Qh, Kh, Vh);

    attn_mma<<<dim3(kT / 64, kH), 128, ATTN_SMEM>>>(Qh, Kh, Vh, cu, Ah);

    gemm_o<<<dim3(kE / 128, kT / 128), 256, GEMM_SMEM>>>(
        Ah, Wh + 3 * (size_t)nW, b[3], out);
}

// round 9
// speedup vs baseline: 2.4994x; 1.0697x over previous
#include <cuda_runtime.h>
#include <cuda_fp16.h>
#include <math.h>
#include <cstdint>

// Problem constants
#define kT 4096
#define kE 1024
#define kH 16
#define kD 64

// ---------------------------------------------------------------------------
// Scratch (__device__ globals; allocation-free rule)
// ---------------------------------------------------------------------------
__device__ __half g_Xh[kT * kE];
__device__ __half g_Wh[4][kE * kE];   // q,k,v,o weights (fp16 hi)
__device__ __half g_Qh[kT * kE];
__device__ __half g_Kh[kT * kE];
__device__ __half g_Vh[kT * kE];
__device__ __half g_Ah[kT * kE];      // attention out

// ---------------------------------------------------------------------------
// Helpers (plain PTX, compute_103-safe)
// ---------------------------------------------------------------------------
__device__ __forceinline__ uint32_t smem_u32(const void* p) {
    uint32_t a;
    asm("{ .reg .u64 t; cvta.to.shared.u64 t, %1; cvt.u32.u64 %0, t; }"
        : "=r"(a) : "l"(p));
    return a;
}

__device__ __forceinline__ void cp16(uint32_t dst, const void* src) {
    asm volatile("cp.async.cg.shared.global [%0], [%1], 16;"
                 :: "r"(dst), "l"(src) : "memory");
}
#define CP_COMMIT() asm volatile("cp.async.commit_group;" ::: "memory")
#define CP_WAIT(n)  asm volatile("cp.async.wait_group %0;" :: "n"(n) : "memory")

__device__ __forceinline__ void ldsm_x4(uint32_t& r0, uint32_t& r1,
                                        uint32_t& r2, uint32_t& r3,
                                        uint32_t addr) {
    asm volatile("ldmatrix.sync.aligned.m8n8.x4.shared.b16 {%0,%1,%2,%3}, [%4];"
                 : "=r"(r0), "=r"(r1), "=r"(r2), "=r"(r3) : "r"(addr));
}

__device__ __forceinline__ void ldsm_x4_trans(uint32_t& r0, uint32_t& r1,
                                              uint32_t& r2, uint32_t& r3,
                                              uint32_t addr) {
    asm volatile("ldmatrix.sync.aligned.m8n8.x4.trans.shared.b16 {%0,%1,%2,%3}, [%4];"
                 : "=r"(r0), "=r"(r1), "=r"(r2), "=r"(r3) : "r"(addr));
}

__device__ __forceinline__ void mma_f16(float& d0, float& d1, float& d2, float& d3,
                                        uint32_t a0, uint32_t a1, uint32_t a2,
                                        uint32_t a3, uint32_t b0, uint32_t b1) {
    asm("mma.sync.aligned.m16n8k16.row.col.f32.f16.f16.f32 "
        "{%0,%1,%2,%3}, {%4,%5,%6,%7}, {%8,%9}, {%0,%1,%2,%3};"
        : "+f"(d0), "+f"(d1), "+f"(d2), "+f"(d3)
        : "r"(a0), "r"(a1), "r"(a2), "r"(a3), "r"(b0), "r"(b1));
}

__device__ __forceinline__ uint32_t pack_f16(float a, float b) {
    __half ha = __float2half_rn(a);
    __half hb = __float2half_rn(b);
    return ((uint32_t)__half_as_ushort(hb) << 16) | __half_as_ushort(ha);
}

// ---------------------------------------------------------------------------
// Elementwise converts
// ---------------------------------------------------------------------------
__global__ void cvt_f16(const float* __restrict__ in, __half* __restrict__ hi,
                        int n) {
    int i = (blockIdx.x * blockDim.x + threadIdx.x) * 4;
    if (i >= n) return;
    float4 x = *(const float4*)(in + i);
    uint2 ph;
    ph.x = pack_f16(x.x, x.y);
    ph.y = pack_f16(x.z, x.w);
    *(uint2*)(hi + i) = ph;
}

__global__ void cvt_w4(const float* __restrict__ w0, const float* __restrict__ w1,
                       const float* __restrict__ w2, const float* __restrict__ w3,
                       __half* __restrict__ hi, int n) {
    const float* src = (blockIdx.y == 0) ? w0 : (blockIdx.y == 1) ? w1
                       : (blockIdx.y == 2) ? w2 : w3;
    __half* dst = hi + (size_t)blockIdx.y * n;
    int i = (blockIdx.x * blockDim.x + threadIdx.x) * 4;
    if (i >= n) return;
    float4 x = *(const float4*)(src + i);
    uint2 ph;
    ph.x = pack_f16(x.x, x.y);
    ph.y = pack_f16(x.z, x.w);
    *(uint2*)(dst + i) = ph;
}

// ---------------------------------------------------------------------------
// Warp-MMA fp16 GEMM-NT + bias, cp.async double-buffered.
// CTA 128x128, 8 warps, K-chunk 64.
// OUTMODE: 0 = fp32 out, 1 = fp16 out. SCALE: multiply result by 0.125 (Q).
// ---------------------------------------------------------------------------
#define KCH 64
#define ASTR 72
#define TILE_B (128 * ASTR * 2)
#define GEMM_SMEM (2 * 2 * TILE_B)     // 73728 B

template <int OUTMODE, bool SCALE>
__device__ __forceinline__ void gemm_body(const __half* __restrict__ Ahg,
                                          const __half* __restrict__ Bhg,
                                          const float* __restrict__ bias,
                                          float* __restrict__ Yf,
                                          __half* __restrict__ Yh) {
    extern __shared__ __half dsm[];

    const int tid = threadIdx.x;
    const int wid = tid >> 5;
    const int lid = tid & 31;
    const int wm = (wid & 3) * 32;
    const int wn = (wid >> 2) * 64;
    const int row0 = blockIdx.y * 128;
    const int col0 = blockIdx.x * 128;

    const uint32_t ubase = smem_u32(dsm);

    float acc[2][8][4];
#pragma unroll
    for (int i = 0; i < 2; i++)
#pragma unroll
        for (int j = 0; j < 8; j++)
#pragma unroll
            for (int c = 0; c < 4; c++) acc[i][j][c] = 0.0f;

    const int lrow = lid & 15;
    const int lkhalf = (lid >> 4) * 8;
    const int bn = (lid >> 4) * 8 + (lid & 7);
    const int bk = ((lid >> 3) & 1) * 8;

#define GEMM_LOAD(stb, k0)                                                    \
    do {                                                                      \
        _Pragma("unroll")                                                     \
        for (int i = 0; i < 4; i++) {                                         \
            int g = tid + i * 256;                                            \
            int r = g >> 3, c8 = (g & 7) * 8;                                 \
            uint32_t so = (stb) + (uint32_t)(r * ASTR + c8) * 2;              \
            cp16(so, Ahg + (size_t)(row0 + r) * kE + (k0) + c8);              \
            cp16(so + TILE_B, Bhg + (size_t)(col0 + r) * kE + (k0) + c8);     \
        }                                                                     \
    } while (0)

    GEMM_LOAD(ubase, 0);
    CP_COMMIT();

    const int NS = kE / KCH;  // 16
    for (int s = 0; s < NS; s++) {
        if (s + 1 < NS) {
            uint32_t stb = ubase + ((s + 1) & 1) * (2 * TILE_B);
            GEMM_LOAD(stb, (s + 1) * KCH);
            CP_COMMIT();
            CP_WAIT(1);
        } else {
            CP_WAIT(0);
        }
        __syncthreads();

        const uint32_t uA = ubase + (s & 1) * (2 * TILE_B);
        const uint32_t uB = uA + TILE_B;

#pragma unroll
        for (int kk = 0; kk < KCH; kk += 16) {
            uint32_t ah[2][4], bh[4][4];
#pragma unroll
            for (int i = 0; i < 2; i++) {
                uint32_t off = (uint32_t)((wm + i * 16 + lrow) * ASTR + kk + lkhalf) * 2;
                ldsm_x4(ah[i][0], ah[i][1], ah[i][2], ah[i][3], uA + off);
            }
#pragma unroll
            for (int p = 0; p < 4; p++) {
                uint32_t boff = (uint32_t)((wn + p * 16 + bn) * ASTR + kk + bk) * 2;
                ldsm_x4(bh[p][0], bh[p][1], bh[p][2], bh[p][3], uB + boff);
            }
#pragma unroll
            for (int p = 0; p < 4; p++)
#pragma unroll
                for (int i = 0; i < 2; i++) {
                    float* d0 = acc[i][p * 2];
                    float* d1 = acc[i][p * 2 + 1];
                    mma_f16(d0[0], d0[1], d0[2], d0[3],
                            ah[i][0], ah[i][1], ah[i][2], ah[i][3],
                            bh[p][0], bh[p][1]);
                    mma_f16(d1[0], d1[1], d1[2], d1[3],
                            ah[i][0], ah[i][1], ah[i][2], ah[i][3],
                            bh[p][2], bh[p][3]);
                }
        }
        __syncthreads();
    }
#undef GEMM_LOAD

    const int erow = lid >> 2;
    const int ecol = (lid & 3) * 2;
#pragma unroll
    for (int i = 0; i < 2; i++) {
        int r = row0 + wm + i * 16 + erow;
#pragma unroll
        for (int j = 0; j < 8; j++) {
            int c = col0 + wn + j * 8 + ecol;
            float b0 = bias[c], b1 = bias[c + 1];
            float v00 = acc[i][j][0] + b0, v01 = acc[i][j][1] + b1;
            float v10 = acc[i][j][2] + b0, v11 = acc[i][j][3] + b1;
            if (SCALE) {
                v00 *= 0.125f; v01 *= 0.125f; v10 *= 0.125f; v11 *= 0.125f;
            }
            if (OUTMODE == 0) {
                *(float2*)(Yf + (size_t)r * kE + c) = make_float2(v00, v01);
                *(float2*)(Yf + (size_t)(r + 8) * kE + c) = make_float2(v10, v11);
            } else {
                *(uint32_t*)(Yh + (size_t)r * kE + c) = pack_f16(v00, v01);
                *(uint32_t*)(Yh + (size_t)(r + 8) * kE + c) = pack_f16(v10, v11);
            }
        }
    }
}

// Fused Q/K/V projection; Q is pre-scaled by D^-0.5.
__global__ __launch_bounds__(256, 2)
void gemm_qkv(const __half* __restrict__ Xh, const __half* __restrict__ Whall,
              const float* __restrict__ bq, const float* __restrict__ bk,
              const float* __restrict__ bv,
              __half* __restrict__ Q, __half* __restrict__ K,
              __half* __restrict__ V) {
    const int z = blockIdx.z;
    const __half* B = Whall + (size_t)z * kE * kE;
    if (z == 0)      gemm_body<1, true>(Xh, B, bq, nullptr, Q);
    else if (z == 1) gemm_body<1, false>(Xh, B, bk, nullptr, K);
    else             gemm_body<1, false>(Xh, B, bv, nullptr, V);
}

__global__ __launch_bounds__(256, 2)
void gemm_o(const __half* __restrict__ Ah, const __half* __restrict__ Wo,
            const float* __restrict__ bias, float* __restrict__ Y) {
    gemm_body<0, false>(Ah, Wo, bias, Y, nullptr);
}

// ---------------------------------------------------------------------------
// Varlen flash attention: S = Q*K (Q pre-scaled), O += P*V (P fp16 hi only).
// Interior k-blocks skip masking entirely.
// ---------------------------------------------------------------------------
#define QSTR 72
#define ATTN_SMEM (13824 * 2 + 2 * 64 * 4)

__global__ __launch_bounds__(128)
void attn_mma(const __half* __restrict__ Qhg,
              const __half* __restrict__ Khg,
              const __half* __restrict__ Vhg,
              const int* __restrict__ cu,
              __half* __restrict__ Oh) {
    extern __shared__ __half sb[];
    __half* sQh = sb;
    __half* sKh = sb + 4608;
    __half* sVh = sb + 9216;
    int* s_lo = (int*)(sb + 13824);
    int* s_hi = s_lo + 64;

    const int tid = threadIdx.x;
    const int wid = tid >> 5;
    const int lid = tid & 31;
    const int q0 = blockIdx.x * 64;
    const int hcol = blockIdx.y * kD;
    const int wm = wid * 16;

    const uint32_t uQh = smem_u32(sQh);
    const uint32_t uKh = smem_u32(sKh);
    const uint32_t uVh = smem_u32(sVh);

    if (tid < 64) {
        int r = q0 + tid;
        int lo = 0, hi = kT;
#pragma unroll
        for (int s = 0; s < 8; s++) {
            int a = cu[s], b = cu[s + 1];
            if (r >= a && r < b) { lo = a; hi = b; }
        }
        s_lo[tid] = lo;
        s_hi[tid] = hi;
    }

#pragma unroll
    for (int i = 0; i < 4; i++) {
        int f = tid + i * 128;
        int r = f >> 3;
        int c8 = (f & 7) * 8;
        size_t g = (size_t)(q0 + r) * kE + hcol + c8;
        *(uint4*)(sQh + r * QSTR + c8) = *(const uint4*)(Qhg + g);
    }
    __syncthreads();

    const int rrow = lid >> 2;
    int row_lo[2], row_hi[2];
    row_lo[0] = s_lo[wm + rrow];      row_hi[0] = s_hi[wm + rrow];
    row_lo[1] = s_lo[wm + rrow + 8];  row_hi[1] = s_hi[wm + rrow + 8];
    const int span_lo = s_lo[0];
    const int span_hi = s_hi[63];

    // Warp-wide interior bounds: [wlo, whi) = intersection of all 16 rows.
    int wlo = max(row_lo[0], row_lo[1]);
    int whi = min(row_hi[0], row_hi[1]);
#pragma unroll
    for (int d = 4; d <= 16; d <<= 1) {
        wlo = max(wlo, __shfl_xor_sync(0xffffffffu, wlo, d));
        whi = min(whi, __shfl_xor_sync(0xffffffffu, whi, d));
    }

    const int lrow = lid & 15;
    const int lkhalf = (lid >> 4) * 8;
    const int bn = (lid >> 4) * 8 + (lid & 7);
    const int bk = ((lid >> 3) & 1) * 8;
    const int vt = lid >> 3;
    const int vr = lid & 7;

    float m[2], l[2], o[8][4];
    m[0] = m[1] = -1e30f;
    l[0] = l[1] = 0.0f;
#pragma unroll
    for (int t = 0; t < 8; t++)
#pragma unroll
        for (int c = 0; c < 4; c++) o[t][c] = 0.0f;

    for (int kb = span_lo; kb < span_hi; kb += 64) {
        __syncthreads();
#pragma unroll
        for (int i = 0; i < 4; i++) {
            int f = tid + i * 128;
            int r = f >> 3;
            int c8 = (f & 7) * 8;
            int kg = kb + r;
            uint4 z = make_uint4(0, 0, 0, 0);
            uint4 vkh = z, vvh = z;
            if (kg < span_hi) {
                size_t g = (size_t)kg * kE + hcol + c8;
                vkh = *(const uint4*)(Khg + g);
                vvh = *(const uint4*)(Vhg + g);
            }
            int so = r * QSTR + c8;
            *(uint4*)(sKh + so) = vkh;
            *(uint4*)(sVh + so) = vvh;
        }
        __syncthreads();

        // ---- S = Q K^T ----
        float s[8][4];
#pragma unroll
        for (int t = 0; t < 8; t++)
#pragma unroll
            for (int c = 0; c < 4; c++) s[t][c] = 0.0f;

#pragma unroll
        for (int kc = 0; kc < 4; kc++) {
            uint32_t qh[4];
            uint32_t aoff = (uint32_t)((wm + lrow) * QSTR + kc * 16 + lkhalf) * 2;
            ldsm_x4(qh[0], qh[1], qh[2], qh[3], uQh + aoff);
            uint32_t kh[4][4];
#pragma unroll
            for (int p = 0; p < 4; p++) {
                uint32_t boff = (uint32_t)((p * 16 + bn) * QSTR + kc * 16 + bk) * 2;
                ldsm_x4(kh[p][0], kh[p][1], kh[p][2], kh[p][3], uKh + boff);
            }
#pragma unroll
            for (int p = 0; p < 4; p++) {
                float* d0 = s[p * 2];
                float* d1 = s[p * 2 + 1];
                mma_f16(d0[0], d0[1], d0[2], d0[3],
                        qh[0], qh[1], qh[2], qh[3], kh[p][0], kh[p][1]);
                mma_f16(d1[0], d1[1], d1[2], d1[3],
                        qh[0], qh[1], qh[2], qh[3], kh[p][2], kh[p][3]);
            }
        }

        // ---- online softmax ----
        const bool interior = (kb >= wlo) && (kb + 64 <= whi);
        const int colb = (lid & 3) * 2;
        if (interior) {
#pragma unroll
            for (int i = 0; i < 2; i++) {
                float rm = -1e30f;
#pragma unroll
                for (int t = 0; t < 8; t++)
                    rm = fmaxf(rm, fmaxf(s[t][2 * i], s[t][2 * i + 1]));
                rm = fmaxf(rm, __shfl_xor_sync(0xffffffffu, rm, 1));
                rm = fmaxf(rm, __shfl_xor_sync(0xffffffffu, rm, 2));

                float mn = fmaxf(m[i], rm);
                float c = __expf(m[i] - mn);
                float rs = 0.0f;
#pragma unroll
                for (int t = 0; t < 8; t++) {
                    float p0 = __expf(s[t][2 * i] - mn);
                    float p1 = __expf(s[t][2 * i + 1] - mn);
                    s[t][2 * i] = p0;
                    s[t][2 * i + 1] = p1;
                    rs += p0 + p1;
                }
                rs += __shfl_xor_sync(0xffffffffu, rs, 1);
                rs += __shfl_xor_sync(0xffffffffu, rs, 2);

                l[i] = l[i] * c + rs;
                m[i] = mn;
#pragma unroll
                for (int t = 0; t < 8; t++) {
                    o[t][2 * i] *= c;
                    o[t][2 * i + 1] *= c;
                }
            }
        } else {
#pragma unroll
            for (int i = 0; i < 2; i++) {
                float rm = -1e30f;
#pragma unroll
                for (int t = 0; t < 8; t++) {
                    int kg0 = kb + t * 8 + colb;
                    float v0 = s[t][2 * i];
                    float v1 = s[t][2 * i + 1];
                    if (kg0 < row_lo[i] || kg0 >= row_hi[i]) v0 = -1e30f;
                    if (kg0 + 1 < row_lo[i] || kg0 + 1 >= row_hi[i]) v1 = -1e30f;
                    s[t][2 * i] = v0;
                    s[t][2 * i + 1] = v1;
                    rm = fmaxf(rm, fmaxf(v0, v1));
                }
                rm = fmaxf(rm, __shfl_xor_sync(0xffffffffu, rm, 1));
                rm = fmaxf(rm, __shfl_xor_sync(0xffffffffu, rm, 2));

                float mn = fmaxf(m[i], rm);
                float c = __expf(m[i] - mn);
                float rs = 0.0f;
#pragma unroll
                for (int t = 0; t < 8; t++) {
                    float v0 = s[t][2 * i];
                    float v1 = s[t][2 * i + 1];
                    float p0 = (v0 <= -1e29f) ? 0.0f : __expf(v0 - mn);
                    float p1 = (v1 <= -1e29f) ? 0.0f : __expf(v1 - mn);
                    s[t][2 * i] = p0;
                    s[t][2 * i + 1] = p1;
                    rs += p0 + p1;
                }
                rs += __shfl_xor_sync(0xffffffffu, rs, 1);
                rs += __shfl_xor_sync(0xffffffffu, rs, 2);

                l[i] = l[i] * c + rs;
                m[i] = mn;
#pragma unroll
                for (int t = 0; t < 8; t++) {
                    o[t][2 * i] *= c;
                    o[t][2 * i + 1] *= c;
                }
            }
        }

        // ---- O += P V (P fp16 hi only) ----
#pragma unroll
        for (int kc = 0; kc < 4; kc++) {
            int t0 = 2 * kc, t1 = 2 * kc + 1;
            uint32_t ph[4];
            ph[0] = pack_f16(s[t0][0], s[t0][1]);
            ph[1] = pack_f16(s[t0][2], s[t0][3]);
            ph[2] = pack_f16(s[t1][0], s[t1][1]);
            ph[3] = pack_f16(s[t1][2], s[t1][3]);
            uint32_t vh[4][4];
#pragma unroll
            for (int dp = 0; dp < 4; dp++) {
                uint32_t voff = (uint32_t)((kc * 16 + (vt & 1) * 8 + vr) * QSTR +
                                           dp * 16 + (vt >> 1) * 8) * 2;
                ldsm_x4_trans(vh[dp][0], vh[dp][1], vh[dp][2], vh[dp][3], uVh + voff);
            }
#pragma unroll
            for (int dp = 0; dp < 4; dp++) {
                float* d0 = o[dp * 2];
                float* d1 = o[dp * 2 + 1];
                mma_f16(d0[0], d0[1], d0[2], d0[3],
                        ph[0], ph[1], ph[2], ph[3], vh[dp][0], vh[dp][1]);
                mma_f16(d1[0], d1[1], d1[2], d1[3],
                        ph[0], ph[1], ph[2], ph[3], vh[dp][2], vh[dp][3]);
            }
        }
    }

    float inv0 = 1.0f / l[0];
    float inv1 = 1.0f / l[1];
    const int colb = (lid & 3) * 2;
#pragma unroll
    for (int t = 0; t < 8; t++) {
        int col = hcol + t * 8 + colb;
        int r0 = q0 + wm + rrow;
        *(uint32_t*)(Oh + (size_t)r0 * kE + col) =
            pack_f16(o[t][0] * inv0, o[t][1] * inv0);
        *(uint32_t*)(Oh + (size_t)(r0 + 8) * kE + col) =
            pack_f16(o[t][2] * inv1, o[t][3] * inv1);
    }
}

// ---------------------------------------------------------------------------
extern "C" void kernel_launch(void* const* d_in, const int* in_sizes, int n_in,
                              void* d_out, int out_size) {
    const float* hs = (const float*)d_in[0];
    const int* cu   = (const int*)d_in[1];
    const float* W[4] = {(const float*)d_in[2], (const float*)d_in[4],
                         (const float*)d_in[6], (const float*)d_in[8]};
    const float* b[4] = {(const float*)d_in[3], (const float*)d_in[5],
                         (const float*)d_in[7], (const float*)d_in[9]};
    float* out = (float*)d_out;

    __half *Xh, *Wh, *Qh, *Kh, *Vh, *Ah;
    cudaGetSymbolAddress((void**)&Xh, g_Xh);
    cudaGetSymbolAddress((void**)&Wh, g_Wh);
    cudaGetSymbolAddress((void**)&Qh, g_Qh);
    cudaGetSymbolAddress((void**)&Kh, g_Kh);
    cudaGetSymbolAddress((void**)&Vh, g_Vh);
    cudaGetSymbolAddress((void**)&Ah, g_Ah);

    cudaFuncSetAttribute(attn_mma,
                         cudaFuncAttributeMaxDynamicSharedMemorySize, ATTN_SMEM);
    cudaFuncSetAttribute(gemm_qkv,
                         cudaFuncAttributeMaxDynamicSharedMemorySize, GEMM_SMEM);
    cudaFuncSetAttribute(gemm_o,
                         cudaFuncAttributeMaxDynamicSharedMemorySize, GEMM_SMEM);

    const int nX = kT * kE;
    const int nW = kE * kE;

    cvt_f16<<<nX / 4 / 256, 256>>>(hs, Xh, nX);
    cvt_w4<<<dim3(nW / 4 / 256, 4), 256>>>(W[0], W[1], W[2], W[3], Wh, nW);

    gemm_qkv<<<dim3(kE / 128, kT / 128, 3), 256, GEMM_SMEM>>>(
        Xh, Wh, b[0], b[1], b[2], Qh, Kh, Vh);

    attn_mma<<<dim3(kT / 64, kH), 128, ATTN_SMEM>>>(Qh, Kh, Vh, cu, Ah);

    gemm_o<<<dim3(kE / 128, kT / 128), 256, GEMM_SMEM>>>(
        Ah, Wh + 3 * (size_t)nW, b[3], out);
}